// round 10
// baseline (speedup 1.0000x reference)
#include <cuda_runtime.h>
#include <cuda_fp16.h>
#include <stdint.h>
#include <math.h>

// Problem dims (fixed)
#define BB 8
#define SS 1024
#define DD 2048
#define HH 16
#define HD 128
#define MTOK (BB * SS)     // 8192
#define BHN (BB * HH)      // 128 batch-heads

// ---------------- scratch (device globals; allocation-free) ----------------
__device__ __half g_Xq [(size_t)MTOK * DD];    // fp16 inputs_q
__device__ __half g_Xkv[(size_t)MTOK * DD];    // fp16 inputs_kv
__device__ __half g_Qh[(size_t)MTOK * DD];     // fp16 Q (pre-scaled)
__device__ __half g_Kh[(size_t)MTOK * DD];
__device__ __half g_Vh[(size_t)MTOK * DD];
__device__ __half g_Ch[(size_t)MTOK * DD];     // fp16 attention context
__device__ __half g_Wh[4][(size_t)DD * DD];    // fp16 transposed weights (N-major)

// ---------------- common PTX helpers ---------------------------------------
__device__ __forceinline__ uint32_t smaddr(const void* p) {
    uint32_t a;
    asm("{ .reg .u64 t; cvta.to.shared.u64 t, %1; cvt.u32.u64 %0, t; }"
        : "=r"(a) : "l"(p));
    return a;
}
__device__ __forceinline__ void ldsm4(uint32_t addr, uint32_t* r) {
    asm volatile("ldmatrix.sync.aligned.m8n8.x4.shared.b16 {%0,%1,%2,%3}, [%4];"
                 : "=r"(r[0]), "=r"(r[1]), "=r"(r[2]), "=r"(r[3]) : "r"(addr));
}
__device__ __forceinline__ void ldsm4t(uint32_t addr, uint32_t* r) {
    asm volatile("ldmatrix.sync.aligned.m8n8.x4.trans.shared.b16 {%0,%1,%2,%3}, [%4];"
                 : "=r"(r[0]), "=r"(r[1]), "=r"(r[2]), "=r"(r[3]) : "r"(addr));
}
__device__ __forceinline__ void mma16816(float* c, const uint32_t* a, const uint32_t* b) {
    asm volatile(
        "mma.sync.aligned.m16n8k16.row.col.f32.f16.f16.f32 "
        "{%0,%1,%2,%3},{%4,%5,%6,%7},{%8,%9},{%0,%1,%2,%3};"
        : "+f"(c[0]), "+f"(c[1]), "+f"(c[2]), "+f"(c[3])
        : "r"(a[0]), "r"(a[1]), "r"(a[2]), "r"(a[3]), "r"(b[0]), "r"(b[1]));
}
__device__ __forceinline__ void cpasync16(uint32_t dst, const void* src) {
    asm volatile("cp.async.ca.shared.global [%0], [%1], 16;"
                 :: "r"(dst), "l"(src) : "memory");
}

// ---------------- mma.sync GEMM, fp16 operands, 256x128 block tile ----------
// D[M,N] = scale * A[M,K] @ B[N,K]^T ; A,B fp16 row-major.
// 256 threads, 8 warps as 4m x 2n, warp tile 64x64. BK=32.
// SMEM: A tile 256r x 64B (16KB), B tile 128r x 64B (8KB); 2 stages = 48KB.
// 16B-chunk swizzle within 64B row: phys = c ^ (row & 3).
#define GT 256
#define BKC 32
#define A_TILE 16384
#define B_TILE 8192
#define STAGE_BYTES (A_TILE + B_TILE)
#define GEMM_SMEM (2 * STAGE_BYTES)     // 48 KB

template <int OUT16>
__global__ __launch_bounds__(GT) void gemm_h(
    const __half* __restrict__ A, long lda,
    const __half* __restrict__ B, long ldb,
    void* __restrict__ Cv, long ldc,
    int K, float scale)
{
    extern __shared__ char sm[];

    const int t = threadIdx.x;
    const int lane = t & 31;
    const int wid = t >> 5;
    const int wm = wid >> 1;          // 0..3  (64-row slab)
    const int wn = wid & 1;           // 0..1  (64-col slab)

    const __half* Ab = A + (size_t)(blockIdx.y * 256) * lda;
    const __half* Bb = B + (size_t)(blockIdx.x * 128) * ldb;

    const int sub = lane >> 3;
    const int rin = lane & 7;

    const int rq = t >> 2;            // 0..63
    const int cq = t & 3;             // 16B chunk

    float acc[4][8][4];
#pragma unroll
    for (int i = 0; i < 4; i++)
#pragma unroll
        for (int j = 0; j < 8; j++)
#pragma unroll
            for (int q = 0; q < 4; q++) acc[i][j][q] = 0.f;

    const int NC = K / BKC;
    const uint32_t smb = smaddr(sm);

    // prologue: stage 0
    {
#pragma unroll
        for (int u = 0; u < 4; u++) {
            int row = rq + u * 64;
            uint32_t off = row * 64 + ((cq ^ (row & 3)) << 4);
            cpasync16(smb + off, Ab + (size_t)row * lda + cq * 8);
        }
#pragma unroll
        for (int u = 0; u < 2; u++) {
            int row = rq + u * 64;
            uint32_t off = row * 64 + ((cq ^ (row & 3)) << 4);
            cpasync16(smb + A_TILE + off, Bb + (size_t)row * ldb + cq * 8);
        }
        asm volatile("cp.async.commit_group;" ::: "memory");
    }

    for (int c = 0; c < NC; c++) {
        if (c + 1 < NC) {
            const int kt = (c + 1) * BKC;
            const uint32_t stb = smb + ((c + 1) & 1) * STAGE_BYTES;
#pragma unroll
            for (int u = 0; u < 4; u++) {
                int row = rq + u * 64;
                uint32_t off = row * 64 + ((cq ^ (row & 3)) << 4);
                cpasync16(stb + off, Ab + (size_t)row * lda + kt + cq * 8);
            }
#pragma unroll
            for (int u = 0; u < 2; u++) {
                int row = rq + u * 64;
                uint32_t off = row * 64 + ((cq ^ (row & 3)) << 4);
                cpasync16(stb + A_TILE + off, Bb + (size_t)row * ldb + kt + cq * 8);
            }
            asm volatile("cp.async.commit_group;" ::: "memory");
            asm volatile("cp.async.wait_group 1;" ::: "memory");
        } else {
            asm volatile("cp.async.wait_group 0;" ::: "memory");
        }
        __syncthreads();

        const uint32_t sA = smb + (c & 1) * STAGE_BYTES;
        const uint32_t sB = sA + A_TILE;

#pragma unroll
        for (int ks = 0; ks < 2; ks++) {
            uint32_t Ahf[4][4], Bhf[4][4];
#pragma unroll
            for (int i = 0; i < 4; i++) {
                int arow = wm * 64 + i * 16 + rin + (sub & 1) * 8;
                int ch = 2 * ks + (sub >> 1);
                ldsm4(sA + arow * 64 + ((ch ^ (arow & 3)) << 4), Ahf[i]);
            }
#pragma unroll
            for (int p = 0; p < 4; p++) {
                int brow = wn * 64 + p * 16 + rin + (sub >> 1) * 8;
                int ch = 2 * ks + (sub & 1);
                ldsm4(sB + brow * 64 + ((ch ^ (brow & 3)) << 4), Bhf[p]);
            }
#pragma unroll
            for (int i = 0; i < 4; i++)
#pragma unroll
                for (int p = 0; p < 4; p++) {
                    mma16816(acc[i][2 * p + 0], Ahf[i], &Bhf[p][0]);
                    mma16816(acc[i][2 * p + 1], Ahf[i], &Bhf[p][2]);
                }
        }
        __syncthreads();
    }

    // epilogue
#pragma unroll
    for (int i = 0; i < 4; i++) {
        int r = blockIdx.y * 256 + wm * 64 + i * 16 + (lane >> 2);
#pragma unroll
        for (int j = 0; j < 8; j++) {
            int cc = blockIdx.x * 128 + wn * 64 + j * 8 + (lane & 3) * 2;
            if (OUT16) {
                __half* Co = (__half*)Cv;
                __half2 h0 = __floats2half2_rn(acc[i][j][0] * scale, acc[i][j][1] * scale);
                __half2 h1 = __floats2half2_rn(acc[i][j][2] * scale, acc[i][j][3] * scale);
                *(uint32_t*)&Co[(size_t)r * ldc + cc] = *(uint32_t*)&h0;
                *(uint32_t*)&Co[(size_t)(r + 8) * ldc + cc] = *(uint32_t*)&h1;
            } else {
                float* Co = (float*)Cv;
                float2 v0, v1;
                v0.x = acc[i][j][0] * scale; v0.y = acc[i][j][1] * scale;
                v1.x = acc[i][j][2] * scale; v1.y = acc[i][j][3] * scale;
                *(float2*)&Co[(size_t)r * ldc + cc] = v0;
                *(float2*)&Co[(size_t)(r + 8) * ldc + cc] = v1;
            }
        }
    }
}

// ---------------- fused flash attention (fp16 ctx out) ----------------------
#define FA_SMEM (32768 + 4 * 32768)

__device__ __forceinline__ uint32_t sw_off(int row, int c) {
    return (uint32_t)(row * 256 + ((c ^ (row & 7)) << 4));
}

__global__ __launch_bounds__(256, 1) void flash_attn(
    const __half* __restrict__ Q, const __half* __restrict__ K,
    const __half* __restrict__ V, __half* __restrict__ O)
{
    extern __shared__ char sm[];
    const uint32_t qs = smaddr(sm);
    const uint32_t ks0 = qs + 32768;
    const uint32_t vs0 = qs + 98304;

    const int t = threadIdx.x;
    const int lane = t & 31;
    const int wid = t >> 5;
    const int q0 = blockIdx.x * 128;
    const int hd0 = blockIdx.y * HD;
    const int tokB = blockIdx.z * SS;

    const __half* Kg = K + (size_t)tokB * DD + hd0;
    const __half* Vg = V + (size_t)tokB * DD + hd0;

    const int lr = t >> 4;
    const int lc = t & 15;
    {
#pragma unroll
        for (int j = 0; j < 8; j++) {
            int row = lr + j * 16;
            cpasync16(ks0 + sw_off(row, lc), Kg + (size_t)row * DD + lc * 8);
        }
#pragma unroll
        for (int j = 0; j < 8; j++) {
            int row = lr + j * 16;
            cpasync16(vs0 + sw_off(row, lc), Vg + (size_t)row * DD + lc * 8);
        }
        asm volatile("cp.async.commit_group;" ::: "memory");
    }

    {
        const __half* qg = Q + (size_t)(tokB + q0) * DD + hd0;
#pragma unroll
        for (int j = 0; j < 8; j++) {
            int row = lr + j * 16;
            uint4 v = *(const uint4*)(qg + (size_t)row * DD + lc * 8);
            *(uint4*)(sm + sw_off(row, lc)) = v;
        }
    }
    __syncthreads();

    uint32_t Qfr[8][4];
    {
        const int rloc = wid * 16 + (lane & 15);
#pragma unroll
        for (int kk = 0; kk < 8; kk++) {
            int c = 2 * kk + (lane >> 4);
            ldsm4(qs + sw_off(rloc, c), Qfr[kk]);
        }
    }

    float accO[16][4];
#pragma unroll
    for (int nt = 0; nt < 16; nt++)
#pragma unroll
        for (int q = 0; q < 4; q++) accO[nt][q] = 0.f;
    float m0 = -1e30f, m1 = -1e30f, l0 = 0.f, l1 = 0.f;

    for (int it = 0; it < SS / 128; it++) {
        const uint32_t ksb = ks0 + (it & 1) * 32768;
        const uint32_t vsb = vs0 + (it & 1) * 32768;

        if (it + 1 < SS / 128) {
            const uint32_t kn = ks0 + ((it + 1) & 1) * 32768;
            const uint32_t vn = vs0 + ((it + 1) & 1) * 32768;
            const __half* kg = Kg + (size_t)(it + 1) * 128 * DD;
            const __half* vg = Vg + (size_t)(it + 1) * 128 * DD;
#pragma unroll
            for (int j = 0; j < 8; j++) {
                int row = lr + j * 16;
                cpasync16(kn + sw_off(row, lc), kg + (size_t)row * DD + lc * 8);
            }
#pragma unroll
            for (int j = 0; j < 8; j++) {
                int row = lr + j * 16;
                cpasync16(vn + sw_off(row, lc), vg + (size_t)row * DD + lc * 8);
            }
            asm volatile("cp.async.commit_group;" ::: "memory");
            asm volatile("cp.async.wait_group 1;" ::: "memory");
        } else {
            asm volatile("cp.async.wait_group 0;" ::: "memory");
        }
        __syncthreads();

        float accS[16][4];
#pragma unroll
        for (int nt = 0; nt < 16; nt++)
#pragma unroll
            for (int q = 0; q < 4; q++) accS[nt][q] = 0.f;

#pragma unroll
        for (int np = 0; np < 8; np++) {
            const int krow = np * 16 + (lane & 7) + ((lane >> 4) << 3);
#pragma unroll
            for (int kk = 0; kk < 8; kk++) {
                uint32_t Bf[4];
                int c = 2 * kk + ((lane >> 3) & 1);
                ldsm4(ksb + sw_off(krow, c), Bf);
                mma16816(accS[2 * np + 0], Qfr[kk], &Bf[0]);
                mma16816(accS[2 * np + 1], Qfr[kk], &Bf[2]);
            }
        }

        float mx0 = -1e30f, mx1 = -1e30f;
#pragma unroll
        for (int nt = 0; nt < 16; nt++) {
            mx0 = fmaxf(mx0, fmaxf(accS[nt][0], accS[nt][1]));
            mx1 = fmaxf(mx1, fmaxf(accS[nt][2], accS[nt][3]));
        }
        mx0 = fmaxf(mx0, __shfl_xor_sync(~0u, mx0, 1));
        mx0 = fmaxf(mx0, __shfl_xor_sync(~0u, mx0, 2));
        mx1 = fmaxf(mx1, __shfl_xor_sync(~0u, mx1, 1));
        mx1 = fmaxf(mx1, __shfl_xor_sync(~0u, mx1, 2));

        float mn0 = fmaxf(m0, mx0), mn1 = fmaxf(m1, mx1);
        float a0 = __expf(m0 - mn0), a1 = __expf(m1 - mn1);
        m0 = mn0; m1 = mn1;

        float s0 = 0.f, s1 = 0.f;
#pragma unroll
        for (int nt = 0; nt < 16; nt++) {
            accS[nt][0] = __expf(accS[nt][0] - m0); s0 += accS[nt][0];
            accS[nt][1] = __expf(accS[nt][1] - m0); s0 += accS[nt][1];
            accS[nt][2] = __expf(accS[nt][2] - m1); s1 += accS[nt][2];
            accS[nt][3] = __expf(accS[nt][3] - m1); s1 += accS[nt][3];
        }
        s0 += __shfl_xor_sync(~0u, s0, 1); s0 += __shfl_xor_sync(~0u, s0, 2);
        s1 += __shfl_xor_sync(~0u, s1, 1); s1 += __shfl_xor_sync(~0u, s1, 2);
        l0 = l0 * a0 + s0;
        l1 = l1 * a1 + s1;

#pragma unroll
        for (int nt = 0; nt < 16; nt++) {
            accO[nt][0] *= a0; accO[nt][1] *= a0;
            accO[nt][2] *= a1; accO[nt][3] *= a1;
        }

#pragma unroll
        for (int kk = 0; kk < 8; kk++) {
            uint32_t Pf[4];
            __half2 p0 = __floats2half2_rn(accS[2 * kk][0], accS[2 * kk][1]);
            __half2 p1 = __floats2half2_rn(accS[2 * kk][2], accS[2 * kk][3]);
            __half2 p2 = __floats2half2_rn(accS[2 * kk + 1][0], accS[2 * kk + 1][1]);
            __half2 p3 = __floats2half2_rn(accS[2 * kk + 1][2], accS[2 * kk + 1][3]);
            Pf[0] = *(uint32_t*)&p0; Pf[1] = *(uint32_t*)&p1;
            Pf[2] = *(uint32_t*)&p2; Pf[3] = *(uint32_t*)&p3;

            const int vrow = kk * 16 + (lane & 15);
#pragma unroll
            for (int nd = 0; nd < 8; nd++) {
                uint32_t Bf[4];
                int c = 2 * nd + (lane >> 4);
                ldsm4t(vsb + sw_off(vrow, c), Bf);
                mma16816(accO[2 * nd + 0], Pf, &Bf[0]);
                mma16816(accO[2 * nd + 1], Pf, &Bf[2]);
            }
        }
        __syncthreads();
    }

    const float i0 = 1.f / l0, i1 = 1.f / l1;
    const int r0 = tokB + q0 + wid * 16 + (lane >> 2);
#pragma unroll
    for (int nt = 0; nt < 16; nt++) {
        int d = hd0 + nt * 8 + (lane & 3) * 2;
        __half2 v0 = __floats2half2_rn(accO[nt][0] * i0, accO[nt][1] * i0);
        __half2 v1 = __floats2half2_rn(accO[nt][2] * i1, accO[nt][3] * i1);
        *(uint32_t*)&O[(size_t)r0 * DD + d] = *(uint32_t*)&v0;
        *(uint32_t*)&O[(size_t)(r0 + 8) * DD + d] = *(uint32_t*)&v1;
    }
}

// ---------------- fp32 -> fp16 transpose (weights) --------------------------
__global__ __launch_bounds__(256) void transpose_h(
    const float* __restrict__ in, __half* __restrict__ out, int R, int C)
{
    __shared__ float tile[32][33];
    int x = blockIdx.x * 32 + threadIdx.x;
    int y0 = blockIdx.y * 32;
#pragma unroll
    for (int i = threadIdx.y; i < 32; i += 8)
        tile[i][threadIdx.x] = in[(size_t)(y0 + i) * C + x];
    __syncthreads();
    int xo = blockIdx.y * 32 + threadIdx.x;
    int yo0 = blockIdx.x * 32;
#pragma unroll
    for (int i = threadIdx.y; i < 32; i += 8)
        out[(size_t)(yo0 + i) * R + xo] = __float2half_rn(tile[threadIdx.x][i]);
}

// ---------------- fp32 -> fp16 elementwise ----------------------------------
__global__ __launch_bounds__(256) void cvt_h(
    const float* __restrict__ in, __half* __restrict__ out)
{
    size_t i = ((size_t)blockIdx.x * 256 + threadIdx.x) * 4;
    float4 v = *(const float4*)(in + i);
    __half2 h0 = __floats2half2_rn(v.x, v.y);
    __half2 h1 = __floats2half2_rn(v.z, v.w);
    *(uint2*)(out + i) = make_uint2(*(uint32_t*)&h0, *(uint32_t*)&h1);
}

// ---------------- launch ----------------------------------------------------
extern "C" void kernel_launch(void* const* d_in, const int* in_sizes, int n_in,
                              void* d_out, int out_size)
{
    const float* inq  = (const float*)d_in[0];
    const float* inkv = (const float*)d_in[1];
    const float* Wq   = (const float*)d_in[2];
    const float* Wk   = (const float*)d_in[3];
    const float* Wv   = (const float*)d_in[4];
    const float* Wo   = (const float*)d_in[5];
    float* out = (float*)d_out;

    __half *pXq, *pXkv, *pQh, *pKh, *pVh, *pCh, *pWh;
    cudaGetSymbolAddress((void**)&pXq,  g_Xq);
    cudaGetSymbolAddress((void**)&pXkv, g_Xkv);
    cudaGetSymbolAddress((void**)&pQh,  g_Qh);
    cudaGetSymbolAddress((void**)&pKh,  g_Kh);
    cudaGetSymbolAddress((void**)&pVh,  g_Vh);
    cudaGetSymbolAddress((void**)&pCh,  g_Ch);
    cudaGetSymbolAddress((void**)&pWh,  g_Wh);
    __half* pWhq = pWh;
    __half* pWhk = pWh + (size_t)DD * DD;
    __half* pWhv = pWh + (size_t)2 * DD * DD;
    __half* pWho = pWh + (size_t)3 * DD * DD;

    cudaFuncSetAttribute(gemm_h<0>, cudaFuncAttributeMaxDynamicSharedMemorySize, GEMM_SMEM);
    cudaFuncSetAttribute(gemm_h<1>, cudaFuncAttributeMaxDynamicSharedMemorySize, GEMM_SMEM);
    cudaFuncSetAttribute(flash_attn, cudaFuncAttributeMaxDynamicSharedMemorySize, FA_SMEM);

    const float qscale = 1.0f / sqrtf((float)HD);
    dim3 tb(32, 8);

    // inputs -> fp16
    const unsigned nv = (unsigned)((size_t)MTOK * DD / 4 / 256);
    cvt_h<<<nv, 256>>>(inq,  pXq);
    cvt_h<<<nv, 256>>>(inkv, pXkv);

    // weights -> fp16, transposed to [N][K]
    transpose_h<<<dim3(DD / 32, DD / 32), tb>>>(Wq, pWhq, DD, DD);
    transpose_h<<<dim3(DD / 32, DD / 32), tb>>>(Wk, pWhk, DD, DD);
    transpose_h<<<dim3(DD / 32, DD / 32), tb>>>(Wv, pWhv, DD, DD);
    transpose_h<<<dim3(DD / 32, DD / 32), tb>>>(Wo, pWho, DD, DD);

    // projections -> fp16 Q/K/V  (block tile 256x128)
    dim3 pg(DD / 128, MTOK / 256);   // (16, 32)
    gemm_h<1><<<pg, GT, GEMM_SMEM>>>(pXq,  DD, pWhq, DD, pQh, DD, DD, qscale);
    gemm_h<1><<<pg, GT, GEMM_SMEM>>>(pXkv, DD, pWhk, DD, pKh, DD, DD, 1.0f);
    gemm_h<1><<<pg, GT, GEMM_SMEM>>>(pXkv, DD, pWhv, DD, pVh, DD, DD, 1.0f);

    // fused attention -> fp16 context
    dim3 fg(SS / 128, HH, BB);
    flash_attn<<<fg, 256, FA_SMEM>>>(pQh, pKh, pVh, pCh);

    // output projection (fp32 out)
    gemm_h<0><<<pg, GT, GEMM_SMEM>>>(pCh, DD, pWho, DD, out, DD, DD, 1.0f);
}

// round 11
// speedup vs baseline: 1.0394x; 1.0394x over previous
#include <cuda_runtime.h>
#include <cuda_fp16.h>
#include <stdint.h>
#include <math.h>

// Problem dims (fixed)
#define BB 8
#define SS 1024
#define DD 2048
#define HH 16
#define HD 128
#define MTOK (BB * SS)     // 8192
#define BHN (BB * HH)      // 128 batch-heads

// ---------------- scratch (device globals; allocation-free) ----------------
__device__ __half g_Xq [(size_t)MTOK * DD];    // fp16 inputs_q
__device__ __half g_Xkv[(size_t)MTOK * DD];    // fp16 inputs_kv
__device__ __half g_Qh[(size_t)MTOK * DD];     // fp16 Q (pre-scaled)
__device__ __half g_Kh[(size_t)MTOK * DD];
__device__ __half g_Vh[(size_t)MTOK * DD];
__device__ __half g_Ch[(size_t)MTOK * DD];     // fp16 attention context
__device__ __half g_Wh[4][(size_t)DD * DD];    // fp16 transposed weights (N-major)

// ---------------- common PTX helpers ---------------------------------------
__device__ __forceinline__ uint32_t smaddr(const void* p) {
    uint32_t a;
    asm("{ .reg .u64 t; cvta.to.shared.u64 t, %1; cvt.u32.u64 %0, t; }"
        : "=r"(a) : "l"(p));
    return a;
}
__device__ __forceinline__ void ldsm4(uint32_t addr, uint32_t* r) {
    asm volatile("ldmatrix.sync.aligned.m8n8.x4.shared.b16 {%0,%1,%2,%3}, [%4];"
                 : "=r"(r[0]), "=r"(r[1]), "=r"(r[2]), "=r"(r[3]) : "r"(addr));
}
__device__ __forceinline__ void ldsm4t(uint32_t addr, uint32_t* r) {
    asm volatile("ldmatrix.sync.aligned.m8n8.x4.trans.shared.b16 {%0,%1,%2,%3}, [%4];"
                 : "=r"(r[0]), "=r"(r[1]), "=r"(r[2]), "=r"(r[3]) : "r"(addr));
}
__device__ __forceinline__ void mma16816(float* c, const uint32_t* a, const uint32_t* b) {
    asm volatile(
        "mma.sync.aligned.m16n8k16.row.col.f32.f16.f16.f32 "
        "{%0,%1,%2,%3},{%4,%5,%6,%7},{%8,%9},{%0,%1,%2,%3};"
        : "+f"(c[0]), "+f"(c[1]), "+f"(c[2]), "+f"(c[3])
        : "r"(a[0]), "r"(a[1]), "r"(a[2]), "r"(a[3]), "r"(b[0]), "r"(b[1]));
}
__device__ __forceinline__ void cpasync16(uint32_t dst, const void* src) {
    asm volatile("cp.async.ca.shared.global [%0], [%1], 16;"
                 :: "r"(dst), "l"(src) : "memory");
}

// ---------------- mma.sync GEMM core, fp16 operands, 3-stage pipeline -------
// D[128,128] tile of scale * A[M,K] @ B[N,K]^T ; A,B fp16 row-major.
// 256 threads, 8 warps: 4m x 2n, warp tile 32x64, BK=32.
// SMEM per stage: A 128r x 64B (8KB) + B 8KB = 16KB; 3 stages = 48KB.
// 16B-chunk swizzle within 64B row: phys = c ^ (row & 3).
#define GT 256
#define BKC 32
#define TILE_B 8192
#define STAGE_BYTES (2 * TILE_B)
#define GEMM_SMEM (3 * STAGE_BYTES)     // 48 KB

__device__ __forceinline__ void issue_stage(
    uint32_t stb, const __half* Ab, const __half* Bb,
    long lda, long ldb, int kt, int rq, int cq)
{
#pragma unroll
    for (int u = 0; u < 2; u++) {
        int row = rq + u * 64;
        uint32_t off = row * 64 + ((cq ^ (row & 3)) << 4);
        cpasync16(stb + off, Ab + (size_t)row * lda + kt + cq * 8);
        cpasync16(stb + TILE_B + off, Bb + (size_t)row * ldb + kt + cq * 8);
    }
    asm volatile("cp.async.commit_group;" ::: "memory");
}

template <int OUT16>
__device__ __forceinline__ void gemm_tile(
    const __half* __restrict__ Ab, const __half* __restrict__ Bb,
    void* __restrict__ Cv, long lda, long ldb, long ldc,
    int K, float scale, char* sm, int bx, int by)
{
    const int t = threadIdx.x;
    const int lane = t & 31;
    const int wid = t >> 5;
    const int wm = wid >> 1;
    const int wn = wid & 1;
    const int sub = lane >> 3;
    const int rin = lane & 7;
    const int rq = t >> 2;            // 0..63
    const int cq = t & 3;             // 16B chunk

    float acc[2][8][4];
#pragma unroll
    for (int i = 0; i < 2; i++)
#pragma unroll
        for (int j = 0; j < 8; j++)
#pragma unroll
            for (int q = 0; q < 4; q++) acc[i][j][q] = 0.f;

    const int NC = K / BKC;
    const uint32_t smb = smaddr(sm);

    // prologue: stages 0, 1
    issue_stage(smb, Ab, Bb, lda, ldb, 0, rq, cq);
    issue_stage(smb + STAGE_BYTES, Ab, Bb, lda, ldb, BKC, rq, cq);

    int stage = 0;   // stage holding chunk c
    int fill = 2;    // stage to fill with chunk c+2

    for (int c = 0; c < NC; c++) {
        if (c + 1 < NC) {
            asm volatile("cp.async.wait_group 1;" ::: "memory");
        } else {
            asm volatile("cp.async.wait_group 0;" ::: "memory");
        }
        __syncthreads();

        if (c + 2 < NC)
            issue_stage(smb + fill * STAGE_BYTES, Ab, Bb, lda, ldb,
                        (c + 2) * BKC, rq, cq);

        const uint32_t sA = smb + stage * STAGE_BYTES;
        const uint32_t sB = sA + TILE_B;

#pragma unroll
        for (int ks = 0; ks < 2; ks++) {
            uint32_t Ahf[2][4], Bhf[4][4];
#pragma unroll
            for (int i = 0; i < 2; i++) {
                int arow = wm * 32 + i * 16 + rin + (sub & 1) * 8;
                int ch = 2 * ks + (sub >> 1);
                ldsm4(sA + arow * 64 + ((ch ^ (arow & 3)) << 4), Ahf[i]);
            }
#pragma unroll
            for (int p = 0; p < 4; p++) {
                int brow = wn * 64 + p * 16 + rin + (sub >> 1) * 8;
                int ch = 2 * ks + (sub & 1);
                ldsm4(sB + brow * 64 + ((ch ^ (brow & 3)) << 4), Bhf[p]);
            }
#pragma unroll
            for (int i = 0; i < 2; i++)
#pragma unroll
                for (int p = 0; p < 4; p++) {
                    mma16816(acc[i][2 * p + 0], Ahf[i], &Bhf[p][0]);
                    mma16816(acc[i][2 * p + 1], Ahf[i], &Bhf[p][2]);
                }
        }

        stage = (stage == 2) ? 0 : stage + 1;
        fill  = (fill  == 2) ? 0 : fill  + 1;
    }

    // epilogue
#pragma unroll
    for (int i = 0; i < 2; i++) {
        int r = by * 128 + wm * 32 + i * 16 + (lane >> 2);
#pragma unroll
        for (int j = 0; j < 8; j++) {
            int cc = bx * 128 + wn * 64 + j * 8 + (lane & 3) * 2;
            if (OUT16) {
                __half* Co = (__half*)Cv;
                __half2 h0 = __floats2half2_rn(acc[i][j][0] * scale, acc[i][j][1] * scale);
                __half2 h1 = __floats2half2_rn(acc[i][j][2] * scale, acc[i][j][3] * scale);
                *(uint32_t*)&Co[(size_t)r * ldc + cc] = *(uint32_t*)&h0;
                *(uint32_t*)&Co[(size_t)(r + 8) * ldc + cc] = *(uint32_t*)&h1;
            } else {
                float* Co = (float*)Cv;
                float2 v0, v1;
                v0.x = acc[i][j][0] * scale; v0.y = acc[i][j][1] * scale;
                v1.x = acc[i][j][2] * scale; v1.y = acc[i][j][3] * scale;
                *(float2*)&Co[(size_t)r * ldc + cc] = v0;
                *(float2*)&Co[(size_t)(r + 8) * ldc + cc] = v1;
            }
        }
    }
}

// fused Q/K/V projection: blockIdx.z selects (input, weight, output, scale)
__global__ __launch_bounds__(GT) void gemm_qkv(
    const __half* __restrict__ Xq, const __half* __restrict__ Xkv,
    const __half* __restrict__ Wbase,
    __half* __restrict__ Qo, __half* __restrict__ Ko, __half* __restrict__ Vo,
    float qscale)
{
    extern __shared__ char sm[];
    const int z = blockIdx.z;
    const __half* A = (z == 0) ? Xq : Xkv;
    const __half* B = Wbase + (size_t)z * DD * DD;
    __half* C = (z == 0) ? Qo : ((z == 1) ? Ko : Vo);
    const float sc = (z == 0) ? qscale : 1.0f;
    gemm_tile<1>(A + (size_t)(blockIdx.y * 128) * DD,
                 B + (size_t)(blockIdx.x * 128) * DD,
                 C, DD, DD, DD, DD, sc, sm, blockIdx.x, blockIdx.y);
}

// output projection (fp32 out)
__global__ __launch_bounds__(GT) void gemm_out(
    const __half* __restrict__ A, const __half* __restrict__ B,
    float* __restrict__ C)
{
    extern __shared__ char sm[];
    gemm_tile<0>(A + (size_t)(blockIdx.y * 128) * DD,
                 B + (size_t)(blockIdx.x * 128) * DD,
                 C, DD, DD, DD, DD, 1.0f, sm, blockIdx.x, blockIdx.y);
}

// ---------------- fused flash attention (fp16 ctx out) ----------------------
#define FA_SMEM (32768 + 4 * 32768)

__device__ __forceinline__ uint32_t sw_off(int row, int c) {
    return (uint32_t)(row * 256 + ((c ^ (row & 7)) << 4));
}

__global__ __launch_bounds__(256, 1) void flash_attn(
    const __half* __restrict__ Q, const __half* __restrict__ K,
    const __half* __restrict__ V, __half* __restrict__ O)
{
    extern __shared__ char sm[];
    const uint32_t qs = smaddr(sm);
    const uint32_t ks0 = qs + 32768;
    const uint32_t vs0 = qs + 98304;

    const int t = threadIdx.x;
    const int lane = t & 31;
    const int wid = t >> 5;
    const int q0 = blockIdx.x * 128;
    const int hd0 = blockIdx.y * HD;
    const int tokB = blockIdx.z * SS;

    const __half* Kg = K + (size_t)tokB * DD + hd0;
    const __half* Vg = V + (size_t)tokB * DD + hd0;

    const int lr = t >> 4;
    const int lc = t & 15;
    {
#pragma unroll
        for (int j = 0; j < 8; j++) {
            int row = lr + j * 16;
            cpasync16(ks0 + sw_off(row, lc), Kg + (size_t)row * DD + lc * 8);
        }
#pragma unroll
        for (int j = 0; j < 8; j++) {
            int row = lr + j * 16;
            cpasync16(vs0 + sw_off(row, lc), Vg + (size_t)row * DD + lc * 8);
        }
        asm volatile("cp.async.commit_group;" ::: "memory");
    }

    {
        const __half* qg = Q + (size_t)(tokB + q0) * DD + hd0;
#pragma unroll
        for (int j = 0; j < 8; j++) {
            int row = lr + j * 16;
            uint4 v = *(const uint4*)(qg + (size_t)row * DD + lc * 8);
            *(uint4*)(sm + sw_off(row, lc)) = v;
        }
    }
    __syncthreads();

    uint32_t Qfr[8][4];
    {
        const int rloc = wid * 16 + (lane & 15);
#pragma unroll
        for (int kk = 0; kk < 8; kk++) {
            int c = 2 * kk + (lane >> 4);
            ldsm4(qs + sw_off(rloc, c), Qfr[kk]);
        }
    }

    float accO[16][4];
#pragma unroll
    for (int nt = 0; nt < 16; nt++)
#pragma unroll
        for (int q = 0; q < 4; q++) accO[nt][q] = 0.f;
    float m0 = -1e30f, m1 = -1e30f, l0 = 0.f, l1 = 0.f;

    for (int it = 0; it < SS / 128; it++) {
        const uint32_t ksb = ks0 + (it & 1) * 32768;
        const uint32_t vsb = vs0 + (it & 1) * 32768;

        if (it + 1 < SS / 128) {
            const uint32_t kn = ks0 + ((it + 1) & 1) * 32768;
            const uint32_t vn = vs0 + ((it + 1) & 1) * 32768;
            const __half* kg = Kg + (size_t)(it + 1) * 128 * DD;
            const __half* vg = Vg + (size_t)(it + 1) * 128 * DD;
#pragma unroll
            for (int j = 0; j < 8; j++) {
                int row = lr + j * 16;
                cpasync16(kn + sw_off(row, lc), kg + (size_t)row * DD + lc * 8);
            }
#pragma unroll
            for (int j = 0; j < 8; j++) {
                int row = lr + j * 16;
                cpasync16(vn + sw_off(row, lc), vg + (size_t)row * DD + lc * 8);
            }
            asm volatile("cp.async.commit_group;" ::: "memory");
            asm volatile("cp.async.wait_group 1;" ::: "memory");
        } else {
            asm volatile("cp.async.wait_group 0;" ::: "memory");
        }
        __syncthreads();

        float accS[16][4];
#pragma unroll
        for (int nt = 0; nt < 16; nt++)
#pragma unroll
            for (int q = 0; q < 4; q++) accS[nt][q] = 0.f;

#pragma unroll
        for (int np = 0; np < 8; np++) {
            const int krow = np * 16 + (lane & 7) + ((lane >> 4) << 3);
#pragma unroll
            for (int kk = 0; kk < 8; kk++) {
                uint32_t Bf[4];
                int c = 2 * kk + ((lane >> 3) & 1);
                ldsm4(ksb + sw_off(krow, c), Bf);
                mma16816(accS[2 * np + 0], Qfr[kk], &Bf[0]);
                mma16816(accS[2 * np + 1], Qfr[kk], &Bf[2]);
            }
        }

        float mx0 = -1e30f, mx1 = -1e30f;
#pragma unroll
        for (int nt = 0; nt < 16; nt++) {
            mx0 = fmaxf(mx0, fmaxf(accS[nt][0], accS[nt][1]));
            mx1 = fmaxf(mx1, fmaxf(accS[nt][2], accS[nt][3]));
        }
        mx0 = fmaxf(mx0, __shfl_xor_sync(~0u, mx0, 1));
        mx0 = fmaxf(mx0, __shfl_xor_sync(~0u, mx0, 2));
        mx1 = fmaxf(mx1, __shfl_xor_sync(~0u, mx1, 1));
        mx1 = fmaxf(mx1, __shfl_xor_sync(~0u, mx1, 2));

        float mn0 = fmaxf(m0, mx0), mn1 = fmaxf(m1, mx1);
        float a0 = __expf(m0 - mn0), a1 = __expf(m1 - mn1);
        m0 = mn0; m1 = mn1;

        float s0 = 0.f, s1 = 0.f;
#pragma unroll
        for (int nt = 0; nt < 16; nt++) {
            accS[nt][0] = __expf(accS[nt][0] - m0); s0 += accS[nt][0];
            accS[nt][1] = __expf(accS[nt][1] - m0); s0 += accS[nt][1];
            accS[nt][2] = __expf(accS[nt][2] - m1); s1 += accS[nt][2];
            accS[nt][3] = __expf(accS[nt][3] - m1); s1 += accS[nt][3];
        }
        s0 += __shfl_xor_sync(~0u, s0, 1); s0 += __shfl_xor_sync(~0u, s0, 2);
        s1 += __shfl_xor_sync(~0u, s1, 1); s1 += __shfl_xor_sync(~0u, s1, 2);
        l0 = l0 * a0 + s0;
        l1 = l1 * a1 + s1;

#pragma unroll
        for (int nt = 0; nt < 16; nt++) {
            accO[nt][0] *= a0; accO[nt][1] *= a0;
            accO[nt][2] *= a1; accO[nt][3] *= a1;
        }

#pragma unroll
        for (int kk = 0; kk < 8; kk++) {
            uint32_t Pf[4];
            __half2 p0 = __floats2half2_rn(accS[2 * kk][0], accS[2 * kk][1]);
            __half2 p1 = __floats2half2_rn(accS[2 * kk][2], accS[2 * kk][3]);
            __half2 p2 = __floats2half2_rn(accS[2 * kk + 1][0], accS[2 * kk + 1][1]);
            __half2 p3 = __floats2half2_rn(accS[2 * kk + 1][2], accS[2 * kk + 1][3]);
            Pf[0] = *(uint32_t*)&p0; Pf[1] = *(uint32_t*)&p1;
            Pf[2] = *(uint32_t*)&p2; Pf[3] = *(uint32_t*)&p3;

            const int vrow = kk * 16 + (lane & 15);
#pragma unroll
            for (int nd = 0; nd < 8; nd++) {
                uint32_t Bf[4];
                int c = 2 * nd + (lane >> 4);
                ldsm4t(vsb + sw_off(vrow, c), Bf);
                mma16816(accO[2 * nd + 0], Pf, &Bf[0]);
                mma16816(accO[2 * nd + 1], Pf, &Bf[2]);
            }
        }
        __syncthreads();
    }

    const float i0 = 1.f / l0, i1 = 1.f / l1;
    const int r0 = tokB + q0 + wid * 16 + (lane >> 2);
#pragma unroll
    for (int nt = 0; nt < 16; nt++) {
        int d = hd0 + nt * 8 + (lane & 3) * 2;
        __half2 v0 = __floats2half2_rn(accO[nt][0] * i0, accO[nt][1] * i0);
        __half2 v1 = __floats2half2_rn(accO[nt][2] * i1, accO[nt][3] * i1);
        *(uint32_t*)&O[(size_t)r0 * DD + d] = *(uint32_t*)&v0;
        *(uint32_t*)&O[(size_t)(r0 + 8) * DD + d] = *(uint32_t*)&v1;
    }
}

// ---------------- fp32 -> fp16 transpose (weights) --------------------------
__global__ __launch_bounds__(256) void transpose_h(
    const float* __restrict__ in, __half* __restrict__ out, int R, int C)
{
    __shared__ float tile[32][33];
    int x = blockIdx.x * 32 + threadIdx.x;
    int y0 = blockIdx.y * 32;
#pragma unroll
    for (int i = threadIdx.y; i < 32; i += 8)
        tile[i][threadIdx.x] = in[(size_t)(y0 + i) * C + x];
    __syncthreads();
    int xo = blockIdx.y * 32 + threadIdx.x;
    int yo0 = blockIdx.x * 32;
#pragma unroll
    for (int i = threadIdx.y; i < 32; i += 8)
        out[(size_t)(yo0 + i) * R + xo] = __float2half_rn(tile[threadIdx.x][i]);
}

// ---------------- fp32 -> fp16 elementwise ----------------------------------
__global__ __launch_bounds__(256) void cvt_h(
    const float* __restrict__ in, __half* __restrict__ out)
{
    size_t i = ((size_t)blockIdx.x * 256 + threadIdx.x) * 4;
    float4 v = *(const float4*)(in + i);
    __half2 h0 = __floats2half2_rn(v.x, v.y);
    __half2 h1 = __floats2half2_rn(v.z, v.w);
    *(uint2*)(out + i) = make_uint2(*(uint32_t*)&h0, *(uint32_t*)&h1);
}

// ---------------- launch ----------------------------------------------------
extern "C" void kernel_launch(void* const* d_in, const int* in_sizes, int n_in,
                              void* d_out, int out_size)
{
    const float* inq  = (const float*)d_in[0];
    const float* inkv = (const float*)d_in[1];
    const float* Wq   = (const float*)d_in[2];
    const float* Wk   = (const float*)d_in[3];
    const float* Wv   = (const float*)d_in[4];
    const float* Wo   = (const float*)d_in[5];
    float* out = (float*)d_out;

    __half *pXq, *pXkv, *pQh, *pKh, *pVh, *pCh, *pWh;
    cudaGetSymbolAddress((void**)&pXq,  g_Xq);
    cudaGetSymbolAddress((void**)&pXkv, g_Xkv);
    cudaGetSymbolAddress((void**)&pQh,  g_Qh);
    cudaGetSymbolAddress((void**)&pKh,  g_Kh);
    cudaGetSymbolAddress((void**)&pVh,  g_Vh);
    cudaGetSymbolAddress((void**)&pCh,  g_Ch);
    cudaGetSymbolAddress((void**)&pWh,  g_Wh);
    __half* pWhq = pWh;
    __half* pWho = pWh + (size_t)3 * DD * DD;

    cudaFuncSetAttribute(gemm_qkv, cudaFuncAttributeMaxDynamicSharedMemorySize, GEMM_SMEM);
    cudaFuncSetAttribute(gemm_out, cudaFuncAttributeMaxDynamicSharedMemorySize, GEMM_SMEM);
    cudaFuncSetAttribute(flash_attn, cudaFuncAttributeMaxDynamicSharedMemorySize, FA_SMEM);

    const float qscale = 1.0f / sqrtf((float)HD);
    dim3 tb(32, 8);

    // inputs -> fp16
    const unsigned nv = (unsigned)((size_t)MTOK * DD / 4 / 256);
    cvt_h<<<nv, 256>>>(inq,  pXq);
    cvt_h<<<nv, 256>>>(inkv, pXkv);

    // weights -> fp16, transposed to [N][K]  (order: Wq, Wk, Wv, Wo in g_Wh)
    transpose_h<<<dim3(DD / 32, DD / 32), tb>>>(Wq, pWh,                        DD, DD);
    transpose_h<<<dim3(DD / 32, DD / 32), tb>>>(Wk, pWh + (size_t)DD * DD,      DD, DD);
    transpose_h<<<dim3(DD / 32, DD / 32), tb>>>(Wv, pWh + (size_t)2 * DD * DD,  DD, DD);
    transpose_h<<<dim3(DD / 32, DD / 32), tb>>>(Wo, pWho,                       DD, DD);

    // fused Q/K/V projections: one launch, z = 0..2
    dim3 pg(DD / 128, MTOK / 128, 3);   // (16, 64, 3)
    gemm_qkv<<<pg, GT, GEMM_SMEM>>>(pXq, pXkv, pWhq, pQh, pKh, pVh, qscale);

    // fused attention -> fp16 context
    dim3 fg(SS / 128, HH, BB);
    flash_attn<<<fg, 256, FA_SMEM>>>(pQh, pKh, pVh, pCh);

    // output projection (fp32 out)
    dim3 og(DD / 128, MTOK / 128, 1);
    gemm_out<<<og, GT, GEMM_SMEM>>>(pCh, pWho, out);
}

// round 12
// speedup vs baseline: 1.0561x; 1.0161x over previous
#include <cuda_runtime.h>
#include <cuda_fp16.h>
#include <stdint.h>
#include <math.h>

// Problem dims (fixed)
#define BB 8
#define SS 1024
#define DD 2048
#define HH 16
#define HD 128
#define MTOK (BB * SS)     // 8192
#define BHN (BB * HH)      // 128 batch-heads

// ---------------- scratch (device globals; allocation-free) ----------------
__device__ __half g_Xq [(size_t)MTOK * DD];    // fp16 inputs_q
__device__ __half g_Xkv[(size_t)MTOK * DD];    // fp16 inputs_kv
__device__ __half g_Qh[(size_t)MTOK * DD];     // fp16 Q (pre-scaled)
__device__ __half g_Kh[(size_t)MTOK * DD];
__device__ __half g_Vh[(size_t)MTOK * DD];
__device__ __half g_Ch[(size_t)MTOK * DD];     // fp16 attention context
__device__ __half g_Wh[4][(size_t)DD * DD];    // fp16 transposed weights (N-major)

// ---------------- common PTX helpers ---------------------------------------
__device__ __forceinline__ uint32_t smaddr(const void* p) {
    uint32_t a;
    asm("{ .reg .u64 t; cvta.to.shared.u64 t, %1; cvt.u32.u64 %0, t; }"
        : "=r"(a) : "l"(p));
    return a;
}
__device__ __forceinline__ void ldsm4(uint32_t addr, uint32_t* r) {
    asm volatile("ldmatrix.sync.aligned.m8n8.x4.shared.b16 {%0,%1,%2,%3}, [%4];"
                 : "=r"(r[0]), "=r"(r[1]), "=r"(r[2]), "=r"(r[3]) : "r"(addr));
}
__device__ __forceinline__ void ldsm4t(uint32_t addr, uint32_t* r) {
    asm volatile("ldmatrix.sync.aligned.m8n8.x4.trans.shared.b16 {%0,%1,%2,%3}, [%4];"
                 : "=r"(r[0]), "=r"(r[1]), "=r"(r[2]), "=r"(r[3]) : "r"(addr));
}
__device__ __forceinline__ void mma16816(float* c, const uint32_t* a, const uint32_t* b) {
    asm volatile(
        "mma.sync.aligned.m16n8k16.row.col.f32.f16.f16.f32 "
        "{%0,%1,%2,%3},{%4,%5,%6,%7},{%8,%9},{%0,%1,%2,%3};"
        : "+f"(c[0]), "+f"(c[1]), "+f"(c[2]), "+f"(c[3])
        : "r"(a[0]), "r"(a[1]), "r"(a[2]), "r"(a[3]), "r"(b[0]), "r"(b[1]));
}
__device__ __forceinline__ void cpasync16(uint32_t dst, const void* src) {
    asm volatile("cp.async.ca.shared.global [%0], [%1], 16;"
                 :: "r"(dst), "l"(src) : "memory");
}

// ---------------- mma.sync GEMM core, fp16 operands, 3-stage pipeline -------
// D[128,128] tile of scale * A[M,K] @ B[N,K]^T ; A,B fp16 row-major.
// 256 threads, 8 warps: 4m x 2n, warp tile 32x64, BK=32.
// SMEM per stage: A 128r x 64B (8KB) + B 8KB = 16KB; 3 stages = 48KB.
// Target 2 CTAs/SM (96KB smem, <=128 regs) for 4 warps/SMSP latency cover.
// 16B-chunk swizzle within 64B row: phys = c ^ (row & 3).
#define GT 256
#define BKC 32
#define TILE_B 8192
#define STAGE_BYTES (2 * TILE_B)
#define GEMM_SMEM (3 * STAGE_BYTES)     // 48 KB

__device__ __forceinline__ void issue_stage(
    uint32_t stb, const __half* Ab, const __half* Bb,
    long lda, long ldb, int kt, int rq, int cq)
{
#pragma unroll
    for (int u = 0; u < 2; u++) {
        int row = rq + u * 64;
        uint32_t off = row * 64 + ((cq ^ (row & 3)) << 4);
        cpasync16(stb + off, Ab + (size_t)row * lda + kt + cq * 8);
        cpasync16(stb + TILE_B + off, Bb + (size_t)row * ldb + kt + cq * 8);
    }
    asm volatile("cp.async.commit_group;" ::: "memory");
}

template <int OUT16>
__device__ __forceinline__ void gemm_tile(
    const __half* __restrict__ Ab, const __half* __restrict__ Bb,
    void* __restrict__ Cv, long lda, long ldb, long ldc,
    int K, float scale, char* sm, int bx, int by)
{
    const int t = threadIdx.x;
    const int lane = t & 31;
    const int wid = t >> 5;
    const int wm = wid >> 1;
    const int wn = wid & 1;
    const int sub = lane >> 3;
    const int rin = lane & 7;
    const int rq = t >> 2;            // 0..63
    const int cq = t & 3;             // 16B chunk

    float acc[2][8][4];
#pragma unroll
    for (int i = 0; i < 2; i++)
#pragma unroll
        for (int j = 0; j < 8; j++)
#pragma unroll
            for (int q = 0; q < 4; q++) acc[i][j][q] = 0.f;

    const int NC = K / BKC;
    const uint32_t smb = smaddr(sm);

    // prologue: stages 0, 1
    issue_stage(smb, Ab, Bb, lda, ldb, 0, rq, cq);
    issue_stage(smb + STAGE_BYTES, Ab, Bb, lda, ldb, BKC, rq, cq);

    int stage = 0;   // stage holding chunk c
    int fill = 2;    // stage to fill with chunk c+2

    for (int c = 0; c < NC; c++) {
        if (c + 1 < NC) {
            asm volatile("cp.async.wait_group 1;" ::: "memory");
        } else {
            asm volatile("cp.async.wait_group 0;" ::: "memory");
        }
        __syncthreads();

        if (c + 2 < NC)
            issue_stage(smb + fill * STAGE_BYTES, Ab, Bb, lda, ldb,
                        (c + 2) * BKC, rq, cq);

        const uint32_t sA = smb + stage * STAGE_BYTES;
        const uint32_t sB = sA + TILE_B;

#pragma unroll
        for (int ks = 0; ks < 2; ks++) {
            uint32_t Ahf[2][4], Bhf[4][4];
#pragma unroll
            for (int i = 0; i < 2; i++) {
                int arow = wm * 32 + i * 16 + rin + (sub & 1) * 8;
                int ch = 2 * ks + (sub >> 1);
                ldsm4(sA + arow * 64 + ((ch ^ (arow & 3)) << 4), Ahf[i]);
            }
#pragma unroll
            for (int p = 0; p < 4; p++) {
                int brow = wn * 64 + p * 16 + rin + (sub >> 1) * 8;
                int ch = 2 * ks + (sub & 1);
                ldsm4(sB + brow * 64 + ((ch ^ (brow & 3)) << 4), Bhf[p]);
            }
#pragma unroll
            for (int i = 0; i < 2; i++)
#pragma unroll
                for (int p = 0; p < 4; p++) {
                    mma16816(acc[i][2 * p + 0], Ahf[i], &Bhf[p][0]);
                    mma16816(acc[i][2 * p + 1], Ahf[i], &Bhf[p][2]);
                }
        }

        stage = (stage == 2) ? 0 : stage + 1;
        fill  = (fill  == 2) ? 0 : fill  + 1;
    }

    // epilogue
#pragma unroll
    for (int i = 0; i < 2; i++) {
        int r = by * 128 + wm * 32 + i * 16 + (lane >> 2);
#pragma unroll
        for (int j = 0; j < 8; j++) {
            int cc = bx * 128 + wn * 64 + j * 8 + (lane & 3) * 2;
            if (OUT16) {
                __half* Co = (__half*)Cv;
                __half2 h0 = __floats2half2_rn(acc[i][j][0] * scale, acc[i][j][1] * scale);
                __half2 h1 = __floats2half2_rn(acc[i][j][2] * scale, acc[i][j][3] * scale);
                *(uint32_t*)&Co[(size_t)r * ldc + cc] = *(uint32_t*)&h0;
                *(uint32_t*)&Co[(size_t)(r + 8) * ldc + cc] = *(uint32_t*)&h1;
            } else {
                float* Co = (float*)Cv;
                float2 v0, v1;
                v0.x = acc[i][j][0] * scale; v0.y = acc[i][j][1] * scale;
                v1.x = acc[i][j][2] * scale; v1.y = acc[i][j][3] * scale;
                *(float2*)&Co[(size_t)r * ldc + cc] = v0;
                *(float2*)&Co[(size_t)(r + 8) * ldc + cc] = v1;
            }
        }
    }
}

// fused Q/K/V projection: blockIdx.z selects (input, weight, output, scale)
__global__ __launch_bounds__(GT, 2) void gemm_qkv(
    const __half* __restrict__ Xq, const __half* __restrict__ Xkv,
    const __half* __restrict__ Wbase,
    __half* __restrict__ Qo, __half* __restrict__ Ko, __half* __restrict__ Vo,
    float qscale)
{
    extern __shared__ char sm[];
    const int z = blockIdx.z;
    const __half* A = (z == 0) ? Xq : Xkv;
    const __half* B = Wbase + (size_t)z * DD * DD;
    __half* C = (z == 0) ? Qo : ((z == 1) ? Ko : Vo);
    const float sc = (z == 0) ? qscale : 1.0f;
    gemm_tile<1>(A + (size_t)(blockIdx.y * 128) * DD,
                 B + (size_t)(blockIdx.x * 128) * DD,
                 C, DD, DD, DD, DD, sc, sm, blockIdx.x, blockIdx.y);
}

// output projection (fp32 out)
__global__ __launch_bounds__(GT, 2) void gemm_out(
    const __half* __restrict__ A, const __half* __restrict__ B,
    float* __restrict__ C)
{
    extern __shared__ char sm[];
    gemm_tile<0>(A + (size_t)(blockIdx.y * 128) * DD,
                 B + (size_t)(blockIdx.x * 128) * DD,
                 C, DD, DD, DD, DD, 1.0f, sm, blockIdx.x, blockIdx.y);
}

// ---------------- fused flash attention (fp16 ctx out) ----------------------
#define FA_SMEM (32768 + 4 * 32768)

__device__ __forceinline__ uint32_t sw_off(int row, int c) {
    return (uint32_t)(row * 256 + ((c ^ (row & 7)) << 4));
}

__global__ __launch_bounds__(256, 1) void flash_attn(
    const __half* __restrict__ Q, const __half* __restrict__ K,
    const __half* __restrict__ V, __half* __restrict__ O)
{
    extern __shared__ char sm[];
    const uint32_t qs = smaddr(sm);
    const uint32_t ks0 = qs + 32768;
    const uint32_t vs0 = qs + 98304;

    const int t = threadIdx.x;
    const int lane = t & 31;
    const int wid = t >> 5;
    const int q0 = blockIdx.x * 128;
    const int hd0 = blockIdx.y * HD;
    const int tokB = blockIdx.z * SS;

    const __half* Kg = K + (size_t)tokB * DD + hd0;
    const __half* Vg = V + (size_t)tokB * DD + hd0;

    const int lr = t >> 4;
    const int lc = t & 15;
    {
#pragma unroll
        for (int j = 0; j < 8; j++) {
            int row = lr + j * 16;
            cpasync16(ks0 + sw_off(row, lc), Kg + (size_t)row * DD + lc * 8);
        }
#pragma unroll
        for (int j = 0; j < 8; j++) {
            int row = lr + j * 16;
            cpasync16(vs0 + sw_off(row, lc), Vg + (size_t)row * DD + lc * 8);
        }
        asm volatile("cp.async.commit_group;" ::: "memory");
    }

    {
        const __half* qg = Q + (size_t)(tokB + q0) * DD + hd0;
#pragma unroll
        for (int j = 0; j < 8; j++) {
            int row = lr + j * 16;
            uint4 v = *(const uint4*)(qg + (size_t)row * DD + lc * 8);
            *(uint4*)(sm + sw_off(row, lc)) = v;
        }
    }
    __syncthreads();

    uint32_t Qfr[8][4];
    {
        const int rloc = wid * 16 + (lane & 15);
#pragma unroll
        for (int kk = 0; kk < 8; kk++) {
            int c = 2 * kk + (lane >> 4);
            ldsm4(qs + sw_off(rloc, c), Qfr[kk]);
        }
    }

    float accO[16][4];
#pragma unroll
    for (int nt = 0; nt < 16; nt++)
#pragma unroll
        for (int q = 0; q < 4; q++) accO[nt][q] = 0.f;
    float m0 = -1e30f, m1 = -1e30f, l0 = 0.f, l1 = 0.f;

    for (int it = 0; it < SS / 128; it++) {
        const uint32_t ksb = ks0 + (it & 1) * 32768;
        const uint32_t vsb = vs0 + (it & 1) * 32768;

        if (it + 1 < SS / 128) {
            const uint32_t kn = ks0 + ((it + 1) & 1) * 32768;
            const uint32_t vn = vs0 + ((it + 1) & 1) * 32768;
            const __half* kg = Kg + (size_t)(it + 1) * 128 * DD;
            const __half* vg = Vg + (size_t)(it + 1) * 128 * DD;
#pragma unroll
            for (int j = 0; j < 8; j++) {
                int row = lr + j * 16;
                cpasync16(kn + sw_off(row, lc), kg + (size_t)row * DD + lc * 8);
            }
#pragma unroll
            for (int j = 0; j < 8; j++) {
                int row = lr + j * 16;
                cpasync16(vn + sw_off(row, lc), vg + (size_t)row * DD + lc * 8);
            }
            asm volatile("cp.async.commit_group;" ::: "memory");
            asm volatile("cp.async.wait_group 1;" ::: "memory");
        } else {
            asm volatile("cp.async.wait_group 0;" ::: "memory");
        }
        __syncthreads();

        float accS[16][4];
#pragma unroll
        for (int nt = 0; nt < 16; nt++)
#pragma unroll
            for (int q = 0; q < 4; q++) accS[nt][q] = 0.f;

#pragma unroll
        for (int np = 0; np < 8; np++) {
            const int krow = np * 16 + (lane & 7) + ((lane >> 4) << 3);
#pragma unroll
            for (int kk = 0; kk < 8; kk++) {
                uint32_t Bf[4];
                int c = 2 * kk + ((lane >> 3) & 1);
                ldsm4(ksb + sw_off(krow, c), Bf);
                mma16816(accS[2 * np + 0], Qfr[kk], &Bf[0]);
                mma16816(accS[2 * np + 1], Qfr[kk], &Bf[2]);
            }
        }

        float mx0 = -1e30f, mx1 = -1e30f;
#pragma unroll
        for (int nt = 0; nt < 16; nt++) {
            mx0 = fmaxf(mx0, fmaxf(accS[nt][0], accS[nt][1]));
            mx1 = fmaxf(mx1, fmaxf(accS[nt][2], accS[nt][3]));
        }
        mx0 = fmaxf(mx0, __shfl_xor_sync(~0u, mx0, 1));
        mx0 = fmaxf(mx0, __shfl_xor_sync(~0u, mx0, 2));
        mx1 = fmaxf(mx1, __shfl_xor_sync(~0u, mx1, 1));
        mx1 = fmaxf(mx1, __shfl_xor_sync(~0u, mx1, 2));

        float mn0 = fmaxf(m0, mx0), mn1 = fmaxf(m1, mx1);
        float a0 = __expf(m0 - mn0), a1 = __expf(m1 - mn1);
        m0 = mn0; m1 = mn1;

        float s0 = 0.f, s1 = 0.f;
#pragma unroll
        for (int nt = 0; nt < 16; nt++) {
            accS[nt][0] = __expf(accS[nt][0] - m0); s0 += accS[nt][0];
            accS[nt][1] = __expf(accS[nt][1] - m0); s0 += accS[nt][1];
            accS[nt][2] = __expf(accS[nt][2] - m1); s1 += accS[nt][2];
            accS[nt][3] = __expf(accS[nt][3] - m1); s1 += accS[nt][3];
        }
        s0 += __shfl_xor_sync(~0u, s0, 1); s0 += __shfl_xor_sync(~0u, s0, 2);
        s1 += __shfl_xor_sync(~0u, s1, 1); s1 += __shfl_xor_sync(~0u, s1, 2);
        l0 = l0 * a0 + s0;
        l1 = l1 * a1 + s1;

#pragma unroll
        for (int nt = 0; nt < 16; nt++) {
            accO[nt][0] *= a0; accO[nt][1] *= a0;
            accO[nt][2] *= a1; accO[nt][3] *= a1;
        }

#pragma unroll
        for (int kk = 0; kk < 8; kk++) {
            uint32_t Pf[4];
            __half2 p0 = __floats2half2_rn(accS[2 * kk][0], accS[2 * kk][1]);
            __half2 p1 = __floats2half2_rn(accS[2 * kk][2], accS[2 * kk][3]);
            __half2 p2 = __floats2half2_rn(accS[2 * kk + 1][0], accS[2 * kk + 1][1]);
            __half2 p3 = __floats2half2_rn(accS[2 * kk + 1][2], accS[2 * kk + 1][3]);
            Pf[0] = *(uint32_t*)&p0; Pf[1] = *(uint32_t*)&p1;
            Pf[2] = *(uint32_t*)&p2; Pf[3] = *(uint32_t*)&p3;

            const int vrow = kk * 16 + (lane & 15);
#pragma unroll
            for (int nd = 0; nd < 8; nd++) {
                uint32_t Bf[4];
                int c = 2 * nd + (lane >> 4);
                ldsm4t(vsb + sw_off(vrow, c), Bf);
                mma16816(accO[2 * nd + 0], Pf, &Bf[0]);
                mma16816(accO[2 * nd + 1], Pf, &Bf[2]);
            }
        }
        __syncthreads();
    }

    const float i0 = 1.f / l0, i1 = 1.f / l1;
    const int r0 = tokB + q0 + wid * 16 + (lane >> 2);
#pragma unroll
    for (int nt = 0; nt < 16; nt++) {
        int d = hd0 + nt * 8 + (lane & 3) * 2;
        __half2 v0 = __floats2half2_rn(accO[nt][0] * i0, accO[nt][1] * i0);
        __half2 v1 = __floats2half2_rn(accO[nt][2] * i1, accO[nt][3] * i1);
        *(uint32_t*)&O[(size_t)r0 * DD + d] = *(uint32_t*)&v0;
        *(uint32_t*)&O[(size_t)(r0 + 8) * DD + d] = *(uint32_t*)&v1;
    }
}

// ---------------- fp32 -> fp16 transpose (weights) --------------------------
__global__ __launch_bounds__(256) void transpose_h(
    const float* __restrict__ in, __half* __restrict__ out, int R, int C)
{
    __shared__ float tile[32][33];
    int x = blockIdx.x * 32 + threadIdx.x;
    int y0 = blockIdx.y * 32;
#pragma unroll
    for (int i = threadIdx.y; i < 32; i += 8)
        tile[i][threadIdx.x] = in[(size_t)(y0 + i) * C + x];
    __syncthreads();
    int xo = blockIdx.y * 32 + threadIdx.x;
    int yo0 = blockIdx.x * 32;
#pragma unroll
    for (int i = threadIdx.y; i < 32; i += 8)
        out[(size_t)(yo0 + i) * R + xo] = __float2half_rn(tile[threadIdx.x][i]);
}

// ---------------- fp32 -> fp16 elementwise ----------------------------------
__global__ __launch_bounds__(256) void cvt_h(
    const float* __restrict__ in, __half* __restrict__ out)
{
    size_t i = ((size_t)blockIdx.x * 256 + threadIdx.x) * 4;
    float4 v = *(const float4*)(in + i);
    __half2 h0 = __floats2half2_rn(v.x, v.y);
    __half2 h1 = __floats2half2_rn(v.z, v.w);
    *(uint2*)(out + i) = make_uint2(*(uint32_t*)&h0, *(uint32_t*)&h1);
}

// ---------------- launch ----------------------------------------------------
extern "C" void kernel_launch(void* const* d_in, const int* in_sizes, int n_in,
                              void* d_out, int out_size)
{
    const float* inq  = (const float*)d_in[0];
    const float* inkv = (const float*)d_in[1];
    const float* Wq   = (const float*)d_in[2];
    const float* Wk   = (const float*)d_in[3];
    const float* Wv   = (const float*)d_in[4];
    const float* Wo   = (const float*)d_in[5];
    float* out = (float*)d_out;

    __half *pXq, *pXkv, *pQh, *pKh, *pVh, *pCh, *pWh;
    cudaGetSymbolAddress((void**)&pXq,  g_Xq);
    cudaGetSymbolAddress((void**)&pXkv, g_Xkv);
    cudaGetSymbolAddress((void**)&pQh,  g_Qh);
    cudaGetSymbolAddress((void**)&pKh,  g_Kh);
    cudaGetSymbolAddress((void**)&pVh,  g_Vh);
    cudaGetSymbolAddress((void**)&pCh,  g_Ch);
    cudaGetSymbolAddress((void**)&pWh,  g_Wh);
    __half* pWhq = pWh;
    __half* pWho = pWh + (size_t)3 * DD * DD;

    cudaFuncSetAttribute(gemm_qkv, cudaFuncAttributeMaxDynamicSharedMemorySize, GEMM_SMEM);
    cudaFuncSetAttribute(gemm_out, cudaFuncAttributeMaxDynamicSharedMemorySize, GEMM_SMEM);
    cudaFuncSetAttribute(flash_attn, cudaFuncAttributeMaxDynamicSharedMemorySize, FA_SMEM);

    const float qscale = 1.0f / sqrtf((float)HD);
    dim3 tb(32, 8);

    // inputs -> fp16
    const unsigned nv = (unsigned)((size_t)MTOK * DD / 4 / 256);
    cvt_h<<<nv, 256>>>(inq,  pXq);
    cvt_h<<<nv, 256>>>(inkv, pXkv);

    // weights -> fp16, transposed to [N][K]  (order: Wq, Wk, Wv, Wo in g_Wh)
    transpose_h<<<dim3(DD / 32, DD / 32), tb>>>(Wq, pWh,                        DD, DD);
    transpose_h<<<dim3(DD / 32, DD / 32), tb>>>(Wk, pWh + (size_t)DD * DD,      DD, DD);
    transpose_h<<<dim3(DD / 32, DD / 32), tb>>>(Wv, pWh + (size_t)2 * DD * DD,  DD, DD);
    transpose_h<<<dim3(DD / 32, DD / 32), tb>>>(Wo, pWho,                       DD, DD);

    // fused Q/K/V projections: one launch, z = 0..2
    dim3 pg(DD / 128, MTOK / 128, 3);   // (16, 64, 3)
    gemm_qkv<<<pg, GT, GEMM_SMEM>>>(pXq, pXkv, pWhq, pQh, pKh, pVh, qscale);

    // fused attention -> fp16 context
    dim3 fg(SS / 128, HH, BB);
    flash_attn<<<fg, 256, FA_SMEM>>>(pQh, pKh, pVh, pCh);

    // output projection (fp32 out)
    dim3 og(DD / 128, MTOK / 128, 1);
    gemm_out<<<og, GT, GEMM_SMEM>>>(pCh, pWho, out);
}

// round 13
// speedup vs baseline: 1.3968x; 1.3226x over previous
#include <cuda_runtime.h>
#include <cuda_fp16.h>
#include <stdint.h>
#include <math.h>

// Problem dims (fixed)
#define BB 8
#define SS 1024
#define DD 2048
#define HH 16
#define HD 128
#define MTOK (BB * SS)     // 8192
#define BHN (BB * HH)      // 128 batch-heads

// ---------------- scratch (device globals; allocation-free) ----------------
__device__ __half g_Xq [(size_t)MTOK * DD];    // fp16 inputs_q
__device__ __half g_Xkv[(size_t)MTOK * DD];    // fp16 inputs_kv
__device__ __half g_Qh[(size_t)MTOK * DD];     // fp16 Q (pre-scaled)
__device__ __half g_Kh[(size_t)MTOK * DD];
__device__ __half g_Vh[(size_t)MTOK * DD];
__device__ __half g_Ch[(size_t)MTOK * DD];     // fp16 attention context
__device__ __half g_Wh[4][(size_t)DD * DD];    // fp16 weights, native [K][N]

// ---------------- common PTX helpers ---------------------------------------
__device__ __forceinline__ uint32_t smaddr(const void* p) {
    uint32_t a;
    asm("{ .reg .u64 t; cvta.to.shared.u64 t, %1; cvt.u32.u64 %0, t; }"
        : "=r"(a) : "l"(p));
    return a;
}
__device__ __forceinline__ void ldsm4(uint32_t addr, uint32_t* r) {
    asm volatile("ldmatrix.sync.aligned.m8n8.x4.shared.b16 {%0,%1,%2,%3}, [%4];"
                 : "=r"(r[0]), "=r"(r[1]), "=r"(r[2]), "=r"(r[3]) : "r"(addr));
}
__device__ __forceinline__ void ldsm4t(uint32_t addr, uint32_t* r) {
    asm volatile("ldmatrix.sync.aligned.m8n8.x4.trans.shared.b16 {%0,%1,%2,%3}, [%4];"
                 : "=r"(r[0]), "=r"(r[1]), "=r"(r[2]), "=r"(r[3]) : "r"(addr));
}
__device__ __forceinline__ void mma16816(float* c, const uint32_t* a, const uint32_t* b) {
    asm volatile(
        "mma.sync.aligned.m16n8k16.row.col.f32.f16.f16.f32 "
        "{%0,%1,%2,%3},{%4,%5,%6,%7},{%8,%9},{%0,%1,%2,%3};"
        : "+f"(c[0]), "+f"(c[1]), "+f"(c[2]), "+f"(c[3])
        : "r"(a[0]), "r"(a[1]), "r"(a[2]), "r"(a[3]), "r"(b[0]), "r"(b[1]));
}
__device__ __forceinline__ void cpasync16(uint32_t dst, const void* src) {
    asm volatile("cp.async.ca.shared.global [%0], [%1], 16;"
                 :: "r"(dst), "l"(src) : "memory");
}

// ---------------- mma.sync GEMM core, fp16, 4-stage pipeline ----------------
// D[128,128] tile of scale * A[M,K] @ W[K,N] ; A fp16 row-major [M][K],
// W fp16 row-major native [K][N] (consumed via ldmatrix.trans).
// 256 threads, 8 warps: 4m x 2n, warp tile 32x64, BK=32.
// Stage: A 128r x 64B (8KB, swizzle c^(row&3)) + B 32r x 256B (8KB,
// swizzle c^(row&7)) = 16KB; 4 stages = 64KB; 2 CTAs/SM.
#define GT 256
#define BKC 32
#define TILE_B 8192
#define STAGE_BYTES (2 * TILE_B)
#define GEMM_SMEM (4 * STAGE_BYTES)     // 64 KB

__device__ __forceinline__ void issue_stage(
    uint32_t stb, const __half* Ab, const __half* Wb,
    long lda, long ldb, int kt, int t)
{
    const int rq = t >> 2;            // A rows 0..63 (+64)
    const int cq = t & 3;
#pragma unroll
    for (int u = 0; u < 2; u++) {
        int row = rq + u * 64;
        uint32_t off = row * 64 + ((cq ^ (row & 3)) << 4);
        cpasync16(stb + off, Ab + (size_t)row * lda + kt + cq * 8);
    }
    const int rb = t >> 4;            // B rows 0..15 (+16)
    const int lb = t & 15;
#pragma unroll
    for (int u = 0; u < 2; u++) {
        int row = rb + u * 16;
        uint32_t off = TILE_B + row * 256 + ((lb ^ (row & 7)) << 4);
        cpasync16(stb + off, Wb + (size_t)(kt + row) * ldb + lb * 8);
    }
    asm volatile("cp.async.commit_group;" ::: "memory");
}

template <int OUT16>
__device__ __forceinline__ void gemm_tile(
    const __half* __restrict__ Ab, const __half* __restrict__ Wb,
    void* __restrict__ Cv, long lda, long ldb, long ldc,
    int K, float scale, char* sm, int bx, int by)
{
    const int t = threadIdx.x;
    const int lane = t & 31;
    const int wid = t >> 5;
    const int wm = wid >> 1;
    const int wn = wid & 1;
    const int sub = lane >> 3;
    const int rin = lane & 7;

    float acc[2][8][4];
#pragma unroll
    for (int i = 0; i < 2; i++)
#pragma unroll
        for (int j = 0; j < 8; j++)
#pragma unroll
            for (int q = 0; q < 4; q++) acc[i][j][q] = 0.f;

    const int NC = K / BKC;
    const uint32_t smb = smaddr(sm);

    // prologue: stages 0..2
    issue_stage(smb,                   Ab, Wb, lda, ldb, 0 * BKC, t);
    issue_stage(smb + 1 * STAGE_BYTES, Ab, Wb, lda, ldb, 1 * BKC, t);
    issue_stage(smb + 2 * STAGE_BYTES, Ab, Wb, lda, ldb, 2 * BKC, t);

    for (int c = 0; c < NC; c++) {
        const int rem = NC - 1 - c;
        if (rem >= 2)      asm volatile("cp.async.wait_group 2;" ::: "memory");
        else if (rem == 1) asm volatile("cp.async.wait_group 1;" ::: "memory");
        else               asm volatile("cp.async.wait_group 0;" ::: "memory");
        __syncthreads();

        if (c + 3 < NC)
            issue_stage(smb + ((c + 3) & 3) * STAGE_BYTES, Ab, Wb, lda, ldb,
                        (c + 3) * BKC, t);

        const uint32_t sA = smb + (c & 3) * STAGE_BYTES;
        const uint32_t sB = sA + TILE_B;

#pragma unroll
        for (int ks = 0; ks < 2; ks++) {
            uint32_t Ahf[2][4], Bhf[4][4];
#pragma unroll
            for (int i = 0; i < 2; i++) {
                int arow = wm * 32 + i * 16 + rin + (sub & 1) * 8;
                int ch = 2 * ks + (sub >> 1);
                ldsm4(sA + arow * 64 + ((ch ^ (arow & 3)) << 4), Ahf[i]);
            }
#pragma unroll
            for (int p = 0; p < 4; p++) {
                int brow = ks * 16 + (lane & 15);
                int cc = wn * 8 + 2 * p + (lane >> 4);
                ldsm4t(sB + brow * 256 + ((cc ^ (brow & 7)) << 4), Bhf[p]);
            }
#pragma unroll
            for (int i = 0; i < 2; i++)
#pragma unroll
                for (int p = 0; p < 4; p++) {
                    mma16816(acc[i][2 * p + 0], Ahf[i], &Bhf[p][0]);
                    mma16816(acc[i][2 * p + 1], Ahf[i], &Bhf[p][2]);
                }
        }
    }

    // epilogue
#pragma unroll
    for (int i = 0; i < 2; i++) {
        int r = by * 128 + wm * 32 + i * 16 + (lane >> 2);
#pragma unroll
        for (int j = 0; j < 8; j++) {
            int cc = bx * 128 + wn * 64 + j * 8 + (lane & 3) * 2;
            if (OUT16) {
                __half* Co = (__half*)Cv;
                __half2 h0 = __floats2half2_rn(acc[i][j][0] * scale, acc[i][j][1] * scale);
                __half2 h1 = __floats2half2_rn(acc[i][j][2] * scale, acc[i][j][3] * scale);
                *(uint32_t*)&Co[(size_t)r * ldc + cc] = *(uint32_t*)&h0;
                *(uint32_t*)&Co[(size_t)(r + 8) * ldc + cc] = *(uint32_t*)&h1;
            } else {
                float* Co = (float*)Cv;
                float2 v0, v1;
                v0.x = acc[i][j][0] * scale; v0.y = acc[i][j][1] * scale;
                v1.x = acc[i][j][2] * scale; v1.y = acc[i][j][3] * scale;
                *(float2*)&Co[(size_t)r * ldc + cc] = v0;
                *(float2*)&Co[(size_t)(r + 8) * ldc + cc] = v1;
            }
        }
    }
}

// fused Q/K/V projection: blockIdx.z selects (input, weight, output, scale)
__global__ __launch_bounds__(GT, 2) void gemm_qkv(
    const __half* __restrict__ Xq, const __half* __restrict__ Xkv,
    const __half* __restrict__ Wbase,
    __half* __restrict__ Qo, __half* __restrict__ Ko, __half* __restrict__ Vo,
    float qscale)
{
    extern __shared__ char sm[];
    const int z = blockIdx.z;
    const __half* A = (z == 0) ? Xq : Xkv;
    const __half* W = Wbase + (size_t)z * DD * DD;
    __half* C = (z == 0) ? Qo : ((z == 1) ? Ko : Vo);
    const float sc = (z == 0) ? qscale : 1.0f;
    gemm_tile<1>(A + (size_t)(blockIdx.y * 128) * DD,
                 W + (size_t)(blockIdx.x * 128),
                 C, DD, DD, DD, DD, sc, sm, blockIdx.x, blockIdx.y);
}

// output projection (fp32 out)
__global__ __launch_bounds__(GT, 2) void gemm_out(
    const __half* __restrict__ A, const __half* __restrict__ W,
    float* __restrict__ C)
{
    extern __shared__ char sm[];
    gemm_tile<0>(A + (size_t)(blockIdx.y * 128) * DD,
                 W + (size_t)(blockIdx.x * 128),
                 C, DD, DD, DD, DD, 1.0f, sm, blockIdx.x, blockIdx.y);
}

// ---------------- fused flash attention (fp16 ctx out) ----------------------
#define FA_SMEM (32768 + 4 * 32768)

__device__ __forceinline__ uint32_t sw_off(int row, int c) {
    return (uint32_t)(row * 256 + ((c ^ (row & 7)) << 4));
}

__global__ __launch_bounds__(256, 1) void flash_attn(
    const __half* __restrict__ Q, const __half* __restrict__ K,
    const __half* __restrict__ V, __half* __restrict__ O)
{
    extern __shared__ char sm[];
    const uint32_t qs = smaddr(sm);
    const uint32_t ks0 = qs + 32768;
    const uint32_t vs0 = qs + 98304;

    const int t = threadIdx.x;
    const int lane = t & 31;
    const int wid = t >> 5;
    const int q0 = blockIdx.x * 128;
    const int hd0 = blockIdx.y * HD;
    const int tokB = blockIdx.z * SS;

    const __half* Kg = K + (size_t)tokB * DD + hd0;
    const __half* Vg = V + (size_t)tokB * DD + hd0;

    const int lr = t >> 4;
    const int lc = t & 15;
    {
#pragma unroll
        for (int j = 0; j < 8; j++) {
            int row = lr + j * 16;
            cpasync16(ks0 + sw_off(row, lc), Kg + (size_t)row * DD + lc * 8);
        }
#pragma unroll
        for (int j = 0; j < 8; j++) {
            int row = lr + j * 16;
            cpasync16(vs0 + sw_off(row, lc), Vg + (size_t)row * DD + lc * 8);
        }
        asm volatile("cp.async.commit_group;" ::: "memory");
    }

    {
        const __half* qg = Q + (size_t)(tokB + q0) * DD + hd0;
#pragma unroll
        for (int j = 0; j < 8; j++) {
            int row = lr + j * 16;
            uint4 v = *(const uint4*)(qg + (size_t)row * DD + lc * 8);
            *(uint4*)(sm + sw_off(row, lc)) = v;
        }
    }
    __syncthreads();

    uint32_t Qfr[8][4];
    {
        const int rloc = wid * 16 + (lane & 15);
#pragma unroll
        for (int kk = 0; kk < 8; kk++) {
            int c = 2 * kk + (lane >> 4);
            ldsm4(qs + sw_off(rloc, c), Qfr[kk]);
        }
    }

    float accO[16][4];
#pragma unroll
    for (int nt = 0; nt < 16; nt++)
#pragma unroll
        for (int q = 0; q < 4; q++) accO[nt][q] = 0.f;
    float m0 = -1e30f, m1 = -1e30f, l0 = 0.f, l1 = 0.f;

    for (int it = 0; it < SS / 128; it++) {
        const uint32_t ksb = ks0 + (it & 1) * 32768;
        const uint32_t vsb = vs0 + (it & 1) * 32768;

        if (it + 1 < SS / 128) {
            const uint32_t kn = ks0 + ((it + 1) & 1) * 32768;
            const uint32_t vn = vs0 + ((it + 1) & 1) * 32768;
            const __half* kg = Kg + (size_t)(it + 1) * 128 * DD;
            const __half* vg = Vg + (size_t)(it + 1) * 128 * DD;
#pragma unroll
            for (int j = 0; j < 8; j++) {
                int row = lr + j * 16;
                cpasync16(kn + sw_off(row, lc), kg + (size_t)row * DD + lc * 8);
            }
#pragma unroll
            for (int j = 0; j < 8; j++) {
                int row = lr + j * 16;
                cpasync16(vn + sw_off(row, lc), vg + (size_t)row * DD + lc * 8);
            }
            asm volatile("cp.async.commit_group;" ::: "memory");
            asm volatile("cp.async.wait_group 1;" ::: "memory");
        } else {
            asm volatile("cp.async.wait_group 0;" ::: "memory");
        }
        __syncthreads();

        float accS[16][4];
#pragma unroll
        for (int nt = 0; nt < 16; nt++)
#pragma unroll
            for (int q = 0; q < 4; q++) accS[nt][q] = 0.f;

#pragma unroll
        for (int np = 0; np < 8; np++) {
            const int krow = np * 16 + (lane & 7) + ((lane >> 4) << 3);
#pragma unroll
            for (int kk = 0; kk < 8; kk++) {
                uint32_t Bf[4];
                int c = 2 * kk + ((lane >> 3) & 1);
                ldsm4(ksb + sw_off(krow, c), Bf);
                mma16816(accS[2 * np + 0], Qfr[kk], &Bf[0]);
                mma16816(accS[2 * np + 1], Qfr[kk], &Bf[2]);
            }
        }

        float mx0 = -1e30f, mx1 = -1e30f;
#pragma unroll
        for (int nt = 0; nt < 16; nt++) {
            mx0 = fmaxf(mx0, fmaxf(accS[nt][0], accS[nt][1]));
            mx1 = fmaxf(mx1, fmaxf(accS[nt][2], accS[nt][3]));
        }
        mx0 = fmaxf(mx0, __shfl_xor_sync(~0u, mx0, 1));
        mx0 = fmaxf(mx0, __shfl_xor_sync(~0u, mx0, 2));
        mx1 = fmaxf(mx1, __shfl_xor_sync(~0u, mx1, 1));
        mx1 = fmaxf(mx1, __shfl_xor_sync(~0u, mx1, 2));

        float mn0 = fmaxf(m0, mx0), mn1 = fmaxf(m1, mx1);
        float a0 = __expf(m0 - mn0), a1 = __expf(m1 - mn1);
        m0 = mn0; m1 = mn1;

        float s0 = 0.f, s1 = 0.f;
#pragma unroll
        for (int nt = 0; nt < 16; nt++) {
            accS[nt][0] = __expf(accS[nt][0] - m0); s0 += accS[nt][0];
            accS[nt][1] = __expf(accS[nt][1] - m0); s0 += accS[nt][1];
            accS[nt][2] = __expf(accS[nt][2] - m1); s1 += accS[nt][2];
            accS[nt][3] = __expf(accS[nt][3] - m1); s1 += accS[nt][3];
        }
        s0 += __shfl_xor_sync(~0u, s0, 1); s0 += __shfl_xor_sync(~0u, s0, 2);
        s1 += __shfl_xor_sync(~0u, s1, 1); s1 += __shfl_xor_sync(~0u, s1, 2);
        l0 = l0 * a0 + s0;
        l1 = l1 * a1 + s1;

#pragma unroll
        for (int nt = 0; nt < 16; nt++) {
            accO[nt][0] *= a0; accO[nt][1] *= a0;
            accO[nt][2] *= a1; accO[nt][3] *= a1;
        }

#pragma unroll
        for (int kk = 0; kk < 8; kk++) {
            uint32_t Pf[4];
            __half2 p0 = __floats2half2_rn(accS[2 * kk][0], accS[2 * kk][1]);
            __half2 p1 = __floats2half2_rn(accS[2 * kk][2], accS[2 * kk][3]);
            __half2 p2 = __floats2half2_rn(accS[2 * kk + 1][0], accS[2 * kk + 1][1]);
            __half2 p3 = __floats2half2_rn(accS[2 * kk + 1][2], accS[2 * kk + 1][3]);
            Pf[0] = *(uint32_t*)&p0; Pf[1] = *(uint32_t*)&p1;
            Pf[2] = *(uint32_t*)&p2; Pf[3] = *(uint32_t*)&p3;

            const int vrow = kk * 16 + (lane & 15);
#pragma unroll
            for (int nd = 0; nd < 8; nd++) {
                uint32_t Bf[4];
                int c = 2 * nd + (lane >> 4);
                ldsm4t(vsb + sw_off(vrow, c), Bf);
                mma16816(accO[2 * nd + 0], Pf, &Bf[0]);
                mma16816(accO[2 * nd + 1], Pf, &Bf[2]);
            }
        }
        __syncthreads();
    }

    const float i0 = 1.f / l0, i1 = 1.f / l1;
    const int r0 = tokB + q0 + wid * 16 + (lane >> 2);
#pragma unroll
    for (int nt = 0; nt < 16; nt++) {
        int d = hd0 + nt * 8 + (lane & 3) * 2;
        __half2 v0 = __floats2half2_rn(accO[nt][0] * i0, accO[nt][1] * i0);
        __half2 v1 = __floats2half2_rn(accO[nt][2] * i1, accO[nt][3] * i1);
        *(uint32_t*)&O[(size_t)r0 * DD + d] = *(uint32_t*)&v0;
        *(uint32_t*)&O[(size_t)(r0 + 8) * DD + d] = *(uint32_t*)&v1;
    }
}

// ---------------- fp32 -> fp16 elementwise ----------------------------------
__global__ __launch_bounds__(256) void cvt_h(
    const float* __restrict__ in, __half* __restrict__ out)
{
    size_t i = ((size_t)blockIdx.x * 256 + threadIdx.x) * 4;
    float4 v = *(const float4*)(in + i);
    __half2 h0 = __floats2half2_rn(v.x, v.y);
    __half2 h1 = __floats2half2_rn(v.z, v.w);
    *(uint2*)(out + i) = make_uint2(*(uint32_t*)&h0, *(uint32_t*)&h1);
}

// fp32 -> fp16 for the 4 weights, one launch (z selects tensor)
__global__ __launch_bounds__(256) void cvt_w4(
    const float* __restrict__ w0, const float* __restrict__ w1,
    const float* __restrict__ w2, const float* __restrict__ w3,
    __half* __restrict__ dst)
{
    const int z = blockIdx.z;
    const float* src = (z == 0) ? w0 : ((z == 1) ? w1 : ((z == 2) ? w2 : w3));
    __half* out = dst + (size_t)z * DD * DD;
    size_t i = ((size_t)blockIdx.x * 256 + threadIdx.x) * 4;
    float4 v = *(const float4*)(src + i);
    __half2 h0 = __floats2half2_rn(v.x, v.y);
    __half2 h1 = __floats2half2_rn(v.z, v.w);
    *(uint2*)(out + i) = make_uint2(*(uint32_t*)&h0, *(uint32_t*)&h1);
}

// ---------------- launch ----------------------------------------------------
extern "C" void kernel_launch(void* const* d_in, const int* in_sizes, int n_in,
                              void* d_out, int out_size)
{
    const float* inq  = (const float*)d_in[0];
    const float* inkv = (const float*)d_in[1];
    const float* Wq   = (const float*)d_in[2];
    const float* Wk   = (const float*)d_in[3];
    const float* Wv   = (const float*)d_in[4];
    const float* Wo   = (const float*)d_in[5];
    float* out = (float*)d_out;

    __half *pXq, *pXkv, *pQh, *pKh, *pVh, *pCh, *pWh;
    cudaGetSymbolAddress((void**)&pXq,  g_Xq);
    cudaGetSymbolAddress((void**)&pXkv, g_Xkv);
    cudaGetSymbolAddress((void**)&pQh,  g_Qh);
    cudaGetSymbolAddress((void**)&pKh,  g_Kh);
    cudaGetSymbolAddress((void**)&pVh,  g_Vh);
    cudaGetSymbolAddress((void**)&pCh,  g_Ch);
    cudaGetSymbolAddress((void**)&pWh,  g_Wh);
    __half* pWho = pWh + (size_t)3 * DD * DD;

    cudaFuncSetAttribute(gemm_qkv, cudaFuncAttributeMaxDynamicSharedMemorySize, GEMM_SMEM);
    cudaFuncSetAttribute(gemm_out, cudaFuncAttributeMaxDynamicSharedMemorySize, GEMM_SMEM);
    cudaFuncSetAttribute(flash_attn, cudaFuncAttributeMaxDynamicSharedMemorySize, FA_SMEM);

    const float qscale = 1.0f / sqrtf((float)HD);

    // inputs -> fp16
    const unsigned nv = (unsigned)((size_t)MTOK * DD / 4 / 256);
    cvt_h<<<nv, 256>>>(inq,  pXq);
    cvt_h<<<nv, 256>>>(inkv, pXkv);

    // weights -> fp16, native [K][N], one launch
    dim3 wg((unsigned)((size_t)DD * DD / 4 / 256), 1, 4);
    cvt_w4<<<wg, 256>>>(Wq, Wk, Wv, Wo, pWh);

    // fused Q/K/V projections: one launch, z = 0..2
    dim3 pg(DD / 128, MTOK / 128, 3);   // (16, 64, 3)
    gemm_qkv<<<pg, GT, GEMM_SMEM>>>(pXq, pXkv, pWh, pQh, pKh, pVh, qscale);

    // fused attention -> fp16 context
    dim3 fg(SS / 128, HH, BB);
    flash_attn<<<fg, 256, FA_SMEM>>>(pQh, pKh, pVh, pCh);

    // output projection (fp32 out)
    dim3 og(DD / 128, MTOK / 128, 1);
    gemm_out<<<og, GT, GEMM_SMEM>>>(pCh, pWho, out);
}

// round 16
// speedup vs baseline: 1.6292x; 1.1664x over previous
#include <cuda_runtime.h>
#include <cuda_fp16.h>
#include <stdint.h>
#include <math.h>

// Problem dims (fixed)
#define BB 8
#define SS 1024
#define DD 2048
#define HH 16
#define HD 128
#define MTOK (BB * SS)     // 8192
#define BHN (BB * HH)      // 128 batch-heads

// ---------------- scratch (device globals; allocation-free) ----------------
__device__ __half g_Xq [(size_t)MTOK * DD];    // fp16 inputs_q
__device__ __half g_Xkv[(size_t)MTOK * DD];    // fp16 inputs_kv
__device__ __half g_Qh[(size_t)MTOK * DD];     // fp16 Q (pre-scaled)
__device__ __half g_Kh[(size_t)MTOK * DD];
__device__ __half g_Vh[(size_t)MTOK * DD];
__device__ __half g_Ch[(size_t)MTOK * DD];     // fp16 attention context
__device__ __half g_Wh[4][(size_t)DD * DD];    // fp16 weights, native [K][N]

// ---------------- common PTX helpers ---------------------------------------
__device__ __forceinline__ uint32_t smaddr(const void* p) {
    uint32_t a;
    asm("{ .reg .u64 t; cvta.to.shared.u64 t, %1; cvt.u32.u64 %0, t; }"
        : "=r"(a) : "l"(p));
    return a;
}
__device__ __forceinline__ void ldsm4(uint32_t addr, uint32_t* r) {
    asm volatile("ldmatrix.sync.aligned.m8n8.x4.shared.b16 {%0,%1,%2,%3}, [%4];"
                 : "=r"(r[0]), "=r"(r[1]), "=r"(r[2]), "=r"(r[3]) : "r"(addr));
}
__device__ __forceinline__ void ldsm4t(uint32_t addr, uint32_t* r) {
    asm volatile("ldmatrix.sync.aligned.m8n8.x4.trans.shared.b16 {%0,%1,%2,%3}, [%4];"
                 : "=r"(r[0]), "=r"(r[1]), "=r"(r[2]), "=r"(r[3]) : "r"(addr));
}
__device__ __forceinline__ void mma16816(float* c, const uint32_t* a, const uint32_t* b) {
    asm volatile(
        "mma.sync.aligned.m16n8k16.row.col.f32.f16.f16.f32 "
        "{%0,%1,%2,%3},{%4,%5,%6,%7},{%8,%9},{%0,%1,%2,%3};"
        : "+f"(c[0]), "+f"(c[1]), "+f"(c[2]), "+f"(c[3])
        : "r"(a[0]), "r"(a[1]), "r"(a[2]), "r"(a[3]), "r"(b[0]), "r"(b[1]));
}
__device__ __forceinline__ void cpasync16(uint32_t dst, const void* src) {
    asm volatile("cp.async.ca.shared.global [%0], [%1], 16;"
                 :: "r"(dst), "l"(src) : "memory");
}

// ---------------- mma.sync GEMM core, fp16, 4-stage pipeline ----------------
// D[128,128] tile of scale * A[M,K] @ W[K,N] ; A fp16 row-major [M][K],
// W fp16 row-major native [K][N] (consumed via ldmatrix.trans).
// 128 threads, 4 warps: 2m x 2n, warp tile 64x64, BK=32.
// Stage: A 128r x 64B (8KB, swizzle c^(row&3)) + B 32r x 256B (8KB,
// swizzle c^(row&7)) = 16KB; 4 stages = 64KB; 2 CTAs/SM.
#define GT 128
#define BKC 32
#define TILE_B 8192
#define STAGE_BYTES (2 * TILE_B)
#define GEMM_SMEM (4 * STAGE_BYTES)     // 64 KB

__device__ __forceinline__ void issue_stage(
    uint32_t stb, const __half* Ab, const __half* Wb,
    long lda, long ldb, int kt, int t)
{
    const int rq = t >> 2;            // A rows 0..31 (+32,+64,+96)
    const int cq = t & 3;
#pragma unroll
    for (int u = 0; u < 4; u++) {
        int row = rq + u * 32;
        uint32_t off = row * 64 + ((cq ^ (row & 3)) << 4);
        cpasync16(stb + off, Ab + (size_t)row * lda + kt + cq * 8);
    }
    const int rb = t >> 4;            // B rows 0..7 (+8,+16,+24)
    const int lb = t & 15;
#pragma unroll
    for (int u = 0; u < 4; u++) {
        int row = rb + u * 8;
        uint32_t off = TILE_B + row * 256 + ((lb ^ (row & 7)) << 4);
        cpasync16(stb + off, Wb + (size_t)(kt + row) * ldb + lb * 8);
    }
    asm volatile("cp.async.commit_group;" ::: "memory");
}

template <int OUT16>
__device__ __forceinline__ void gemm_tile(
    const __half* __restrict__ Ab, const __half* __restrict__ Wb,
    void* __restrict__ Cv, long lda, long ldb, long ldc,
    int K, float scale, char* sm, int bx, int by)
{
    const int t = threadIdx.x;
    const int lane = t & 31;
    const int wid = t >> 5;           // 0..3
    const int wm = wid >> 1;          // 0..1 (64-row slab)
    const int wn = wid & 1;           // 0..1 (64-col slab)
    const int sub = lane >> 3;
    const int rin = lane & 7;

    float acc[4][8][4];
#pragma unroll
    for (int i = 0; i < 4; i++)
#pragma unroll
        for (int j = 0; j < 8; j++)
#pragma unroll
            for (int q = 0; q < 4; q++) acc[i][j][q] = 0.f;

    const int NC = K / BKC;
    const uint32_t smb = smaddr(sm);

    // prologue: stages 0..2
    issue_stage(smb,                   Ab, Wb, lda, ldb, 0 * BKC, t);
    issue_stage(smb + 1 * STAGE_BYTES, Ab, Wb, lda, ldb, 1 * BKC, t);
    issue_stage(smb + 2 * STAGE_BYTES, Ab, Wb, lda, ldb, 2 * BKC, t);

    for (int c = 0; c < NC; c++) {
        const int rem = NC - 1 - c;
        if (rem >= 2)      asm volatile("cp.async.wait_group 2;" ::: "memory");
        else if (rem == 1) asm volatile("cp.async.wait_group 1;" ::: "memory");
        else               asm volatile("cp.async.wait_group 0;" ::: "memory");
        __syncthreads();

        if (c + 3 < NC)
            issue_stage(smb + ((c + 3) & 3) * STAGE_BYTES, Ab, Wb, lda, ldb,
                        (c + 3) * BKC, t);

        const uint32_t sA = smb + (c & 3) * STAGE_BYTES;
        const uint32_t sB = sA + TILE_B;

#pragma unroll
        for (int ks = 0; ks < 2; ks++) {
            uint32_t Ahf[4][4], Bhf[4][4];
#pragma unroll
            for (int i = 0; i < 4; i++) {
                int arow = wm * 64 + i * 16 + rin + (sub & 1) * 8;
                int ch = 2 * ks + (sub >> 1);
                ldsm4(sA + arow * 64 + ((ch ^ (arow & 3)) << 4), Ahf[i]);
            }
#pragma unroll
            for (int p = 0; p < 4; p++) {
                int brow = ks * 16 + (lane & 15);
                int cc = wn * 8 + 2 * p + (lane >> 4);
                ldsm4t(sB + brow * 256 + ((cc ^ (brow & 7)) << 4), Bhf[p]);
            }
#pragma unroll
            for (int i = 0; i < 4; i++)
#pragma unroll
                for (int p = 0; p < 4; p++) {
                    mma16816(acc[i][2 * p + 0], Ahf[i], &Bhf[p][0]);
                    mma16816(acc[i][2 * p + 1], Ahf[i], &Bhf[p][2]);
                }
        }
    }

    // epilogue
#pragma unroll
    for (int i = 0; i < 4; i++) {
        int r = by * 128 + wm * 64 + i * 16 + (lane >> 2);
#pragma unroll
        for (int j = 0; j < 8; j++) {
            int cc = bx * 128 + wn * 64 + j * 8 + (lane & 3) * 2;
            if (OUT16) {
                __half* Co = (__half*)Cv;
                __half2 h0 = __floats2half2_rn(acc[i][j][0] * scale, acc[i][j][1] * scale);
                __half2 h1 = __floats2half2_rn(acc[i][j][2] * scale, acc[i][j][3] * scale);
                *(uint32_t*)&Co[(size_t)r * ldc + cc] = *(uint32_t*)&h0;
                *(uint32_t*)&Co[(size_t)(r + 8) * ldc + cc] = *(uint32_t*)&h1;
            } else {
                float* Co = (float*)Cv;
                float2 v0, v1;
                v0.x = acc[i][j][0] * scale; v0.y = acc[i][j][1] * scale;
                v1.x = acc[i][j][2] * scale; v1.y = acc[i][j][3] * scale;
                *(float2*)&Co[(size_t)r * ldc + cc] = v0;
                *(float2*)&Co[(size_t)(r + 8) * ldc + cc] = v1;
            }
        }
    }
}

// fused Q/K/V projection: blockIdx.z selects (input, weight, output, scale)
__global__ __launch_bounds__(GT, 2) void gemm_qkv(
    const __half* __restrict__ Xq, const __half* __restrict__ Xkv,
    const __half* __restrict__ Wbase,
    __half* __restrict__ Qo, __half* __restrict__ Ko, __half* __restrict__ Vo,
    float qscale)
{
    extern __shared__ char sm[];
    const int z = blockIdx.z;
    const __half* A = (z == 0) ? Xq : Xkv;
    const __half* W = Wbase + (size_t)z * DD * DD;
    __half* C = (z == 0) ? Qo : ((z == 1) ? Ko : Vo);
    const float sc = (z == 0) ? qscale : 1.0f;
    gemm_tile<1>(A + (size_t)(blockIdx.y * 128) * DD,
                 W + (size_t)(blockIdx.x * 128),
                 C, DD, DD, DD, DD, sc, sm, blockIdx.x, blockIdx.y);
}

// output projection (fp32 out)
__global__ __launch_bounds__(GT, 2) void gemm_out(
    const __half* __restrict__ A, const __half* __restrict__ W,
    float* __restrict__ C)
{
    extern __shared__ char sm[];
    gemm_tile<0>(A + (size_t)(blockIdx.y * 128) * DD,
                 W + (size_t)(blockIdx.x * 128),
                 C, DD, DD, DD, DD, 1.0f, sm, blockIdx.x, blockIdx.y);
}

// ---------------- fused flash attention (fp16 ctx out) ----------------------
#define FA_SMEM (32768 + 4 * 32768)

__device__ __forceinline__ uint32_t sw_off(int row, int c) {
    return (uint32_t)(row * 256 + ((c ^ (row & 7)) << 4));
}

__global__ __launch_bounds__(256, 1) void flash_attn(
    const __half* __restrict__ Q, const __half* __restrict__ K,
    const __half* __restrict__ V, __half* __restrict__ O)
{
    extern __shared__ char sm[];
    const uint32_t qs = smaddr(sm);
    const uint32_t ks0 = qs + 32768;
    const uint32_t vs0 = qs + 98304;

    const int t = threadIdx.x;
    const int lane = t & 31;
    const int wid = t >> 5;
    const int q0 = blockIdx.x * 128;
    const int hd0 = blockIdx.y * HD;
    const int tokB = blockIdx.z * SS;

    const __half* Kg = K + (size_t)tokB * DD + hd0;
    const __half* Vg = V + (size_t)tokB * DD + hd0;

    const int lr = t >> 4;
    const int lc = t & 15;
    {
#pragma unroll
        for (int j = 0; j < 8; j++) {
            int row = lr + j * 16;
            cpasync16(ks0 + sw_off(row, lc), Kg + (size_t)row * DD + lc * 8);
        }
#pragma unroll
        for (int j = 0; j < 8; j++) {
            int row = lr + j * 16;
            cpasync16(vs0 + sw_off(row, lc), Vg + (size_t)row * DD + lc * 8);
        }
        asm volatile("cp.async.commit_group;" ::: "memory");
    }

    {
        const __half* qg = Q + (size_t)(tokB + q0) * DD + hd0;
#pragma unroll
        for (int j = 0; j < 8; j++) {
            int row = lr + j * 16;
            uint4 v = *(const uint4*)(qg + (size_t)row * DD + lc * 8);
            *(uint4*)(sm + sw_off(row, lc)) = v;
        }
    }
    __syncthreads();

    uint32_t Qfr[8][4];
    {
        const int rloc = wid * 16 + (lane & 15);
#pragma unroll
        for (int kk = 0; kk < 8; kk++) {
            int c = 2 * kk + (lane >> 4);
            ldsm4(qs + sw_off(rloc, c), Qfr[kk]);
        }
    }

    float accO[16][4];
#pragma unroll
    for (int nt = 0; nt < 16; nt++)
#pragma unroll
        for (int q = 0; q < 4; q++) accO[nt][q] = 0.f;
    float m0 = -1e30f, m1 = -1e30f, l0 = 0.f, l1 = 0.f;

    for (int it = 0; it < SS / 128; it++) {
        const uint32_t ksb = ks0 + (it & 1) * 32768;
        const uint32_t vsb = vs0 + (it & 1) * 32768;

        if (it + 1 < SS / 128) {
            const uint32_t kn = ks0 + ((it + 1) & 1) * 32768;
            const uint32_t vn = vs0 + ((it + 1) & 1) * 32768;
            const __half* kg = Kg + (size_t)(it + 1) * 128 * DD;
            const __half* vg = Vg + (size_t)(it + 1) * 128 * DD;
#pragma unroll
            for (int j = 0; j < 8; j++) {
                int row = lr + j * 16;
                cpasync16(kn + sw_off(row, lc), kg + (size_t)row * DD + lc * 8);
            }
#pragma unroll
            for (int j = 0; j < 8; j++) {
                int row = lr + j * 16;
                cpasync16(vn + sw_off(row, lc), vg + (size_t)row * DD + lc * 8);
            }
            asm volatile("cp.async.commit_group;" ::: "memory");
            asm volatile("cp.async.wait_group 1;" ::: "memory");
        } else {
            asm volatile("cp.async.wait_group 0;" ::: "memory");
        }
        __syncthreads();

        float accS[16][4];
#pragma unroll
        for (int nt = 0; nt < 16; nt++)
#pragma unroll
            for (int q = 0; q < 4; q++) accS[nt][q] = 0.f;

#pragma unroll
        for (int np = 0; np < 8; np++) {
            const int krow = np * 16 + (lane & 7) + ((lane >> 4) << 3);
#pragma unroll
            for (int kk = 0; kk < 8; kk++) {
                uint32_t Bf[4];
                int c = 2 * kk + ((lane >> 3) & 1);
                ldsm4(ksb + sw_off(krow, c), Bf);
                mma16816(accS[2 * np + 0], Qfr[kk], &Bf[0]);
                mma16816(accS[2 * np + 1], Qfr[kk], &Bf[2]);
            }
        }

        float mx0 = -1e30f, mx1 = -1e30f;
#pragma unroll
        for (int nt = 0; nt < 16; nt++) {
            mx0 = fmaxf(mx0, fmaxf(accS[nt][0], accS[nt][1]));
            mx1 = fmaxf(mx1, fmaxf(accS[nt][2], accS[nt][3]));
        }
        mx0 = fmaxf(mx0, __shfl_xor_sync(~0u, mx0, 1));
        mx0 = fmaxf(mx0, __shfl_xor_sync(~0u, mx0, 2));
        mx1 = fmaxf(mx1, __shfl_xor_sync(~0u, mx1, 1));
        mx1 = fmaxf(mx1, __shfl_xor_sync(~0u, mx1, 2));

        float mn0 = fmaxf(m0, mx0), mn1 = fmaxf(m1, mx1);
        float a0 = __expf(m0 - mn0), a1 = __expf(m1 - mn1);
        m0 = mn0; m1 = mn1;

        float s0 = 0.f, s1 = 0.f;
#pragma unroll
        for (int nt = 0; nt < 16; nt++) {
            accS[nt][0] = __expf(accS[nt][0] - m0); s0 += accS[nt][0];
            accS[nt][1] = __expf(accS[nt][1] - m0); s0 += accS[nt][1];
            accS[nt][2] = __expf(accS[nt][2] - m1); s1 += accS[nt][2];
            accS[nt][3] = __expf(accS[nt][3] - m1); s1 += accS[nt][3];
        }
        s0 += __shfl_xor_sync(~0u, s0, 1); s0 += __shfl_xor_sync(~0u, s0, 2);
        s1 += __shfl_xor_sync(~0u, s1, 1); s1 += __shfl_xor_sync(~0u, s1, 2);
        l0 = l0 * a0 + s0;
        l1 = l1 * a1 + s1;

#pragma unroll
        for (int nt = 0; nt < 16; nt++) {
            accO[nt][0] *= a0; accO[nt][1] *= a0;
            accO[nt][2] *= a1; accO[nt][3] *= a1;
        }

#pragma unroll
        for (int kk = 0; kk < 8; kk++) {
            uint32_t Pf[4];
            __half2 p0 = __floats2half2_rn(accS[2 * kk][0], accS[2 * kk][1]);
            __half2 p1 = __floats2half2_rn(accS[2 * kk][2], accS[2 * kk][3]);
            __half2 p2 = __floats2half2_rn(accS[2 * kk + 1][0], accS[2 * kk + 1][1]);
            __half2 p3 = __floats2half2_rn(accS[2 * kk + 1][2], accS[2 * kk + 1][3]);
            Pf[0] = *(uint32_t*)&p0; Pf[1] = *(uint32_t*)&p1;
            Pf[2] = *(uint32_t*)&p2; Pf[3] = *(uint32_t*)&p3;

            const int vrow = kk * 16 + (lane & 15);
#pragma unroll
            for (int nd = 0; nd < 8; nd++) {
                uint32_t Bf[4];
                int c = 2 * nd + (lane >> 4);
                ldsm4t(vsb + sw_off(vrow, c), Bf);
                mma16816(accO[2 * nd + 0], Pf, &Bf[0]);
                mma16816(accO[2 * nd + 1], Pf, &Bf[2]);
            }
        }
        __syncthreads();
    }

    const float i0 = 1.f / l0, i1 = 1.f / l1;
    const int r0 = tokB + q0 + wid * 16 + (lane >> 2);
#pragma unroll
    for (int nt = 0; nt < 16; nt++) {
        int d = hd0 + nt * 8 + (lane & 3) * 2;
        __half2 v0 = __floats2half2_rn(accO[nt][0] * i0, accO[nt][1] * i0);
        __half2 v1 = __floats2half2_rn(accO[nt][2] * i1, accO[nt][3] * i1);
        *(uint32_t*)&O[(size_t)r0 * DD + d] = *(uint32_t*)&v0;
        *(uint32_t*)&O[(size_t)(r0 + 8) * DD + d] = *(uint32_t*)&v1;
    }
}

// ---------------- fp32 -> fp16 elementwise ----------------------------------
__global__ __launch_bounds__(256) void cvt_h(
    const float* __restrict__ in, __half* __restrict__ out)
{
    size_t i = ((size_t)blockIdx.x * 256 + threadIdx.x) * 4;
    float4 v = *(const float4*)(in + i);
    __half2 h0 = __floats2half2_rn(v.x, v.y);
    __half2 h1 = __floats2half2_rn(v.z, v.w);
    *(uint2*)(out + i) = make_uint2(*(uint32_t*)&h0, *(uint32_t*)&h1);
}

// fp32 -> fp16 for the 4 weights, one launch (z selects tensor)
__global__ __launch_bounds__(256) void cvt_w4(
    const float* __restrict__ w0, const float* __restrict__ w1,
    const float* __restrict__ w2, const float* __restrict__ w3,
    __half* __restrict__ dst)
{
    const int z = blockIdx.z;
    const float* src = (z == 0) ? w0 : ((z == 1) ? w1 : ((z == 2) ? w2 : w3));
    __half* out = dst + (size_t)z * DD * DD;
    size_t i = ((size_t)blockIdx.x * 256 + threadIdx.x) * 4;
    float4 v = *(const float4*)(src + i);
    __half2 h0 = __floats2half2_rn(v.x, v.y);
    __half2 h1 = __floats2half2_rn(v.z, v.w);
    *(uint2*)(out + i) = make_uint2(*(uint32_t*)&h0, *(uint32_t*)&h1);
}

// ---------------- launch ----------------------------------------------------
extern "C" void kernel_launch(void* const* d_in, const int* in_sizes, int n_in,
                              void* d_out, int out_size)
{
    const float* inq  = (const float*)d_in[0];
    const float* inkv = (const float*)d_in[1];
    const float* Wq   = (const float*)d_in[2];
    const float* Wk   = (const float*)d_in[3];
    const float* Wv   = (const float*)d_in[4];
    const float* Wo   = (const float*)d_in[5];
    float* out = (float*)d_out;

    __half *pXq, *pXkv, *pQh, *pKh, *pVh, *pCh, *pWh;
    cudaGetSymbolAddress((void**)&pXq,  g_Xq);
    cudaGetSymbolAddress((void**)&pXkv, g_Xkv);
    cudaGetSymbolAddress((void**)&pQh,  g_Qh);
    cudaGetSymbolAddress((void**)&pKh,  g_Kh);
    cudaGetSymbolAddress((void**)&pVh,  g_Vh);
    cudaGetSymbolAddress((void**)&pCh,  g_Ch);
    cudaGetSymbolAddress((void**)&pWh,  g_Wh);
    __half* pWho = pWh + (size_t)3 * DD * DD;

    cudaFuncSetAttribute(gemm_qkv, cudaFuncAttributeMaxDynamicSharedMemorySize, GEMM_SMEM);
    cudaFuncSetAttribute(gemm_out, cudaFuncAttributeMaxDynamicSharedMemorySize, GEMM_SMEM);
    cudaFuncSetAttribute(flash_attn, cudaFuncAttributeMaxDynamicSharedMemorySize, FA_SMEM);

    const float qscale = 1.0f / sqrtf((float)HD);

    // inputs -> fp16
    const unsigned nv = (unsigned)((size_t)MTOK * DD / 4 / 256);
    cvt_h<<<nv, 256>>>(inq,  pXq);
    cvt_h<<<nv, 256>>>(inkv, pXkv);

    // weights -> fp16, native [K][N], one launch
    dim3 wg((unsigned)((size_t)DD * DD / 4 / 256), 1, 4);
    cvt_w4<<<wg, 256>>>(Wq, Wk, Wv, Wo, pWh);

    // fused Q/K/V projections: one launch, z = 0..2
    dim3 pg(DD / 128, MTOK / 128, 3);   // (16, 64, 3)
    gemm_qkv<<<pg, GT, GEMM_SMEM>>>(pXq, pXkv, pWh, pQh, pKh, pVh, qscale);

    // fused attention -> fp16 context
    dim3 fg(SS / 128, HH, BB);
    flash_attn<<<fg, 256, FA_SMEM>>>(pQh, pKh, pVh, pCh);

    // output projection (fp32 out)
    dim3 og(DD / 128, MTOK / 128, 1);
    gemm_out<<<og, GT, GEMM_SMEM>>>(pCh, pWho, out);
}